// round 8
// baseline (speedup 1.0000x reference)
#include <cuda_runtime.h>
#include <cuda_fp16.h>
#include <cstdint>

// ---------------------------------------------------------------------------
// Problem constants
// ---------------------------------------------------------------------------
#define B_ 2
#define S_ 2048
#define H_ 16
#define D_ 128
#define HID_ 2048
#define M_ (B_ * S_)   // 4096

// Scratch (device globals — allocation-free per harness rules)
__device__ float g_q[(size_t)B_ * H_ * S_ * D_];   // fp32 Q pre-rope [b,h,s,d]
__device__ float g_k[(size_t)B_ * H_ * S_ * D_];   // fp32 K pre-rope
__device__ float g_scl[8];                         // [0..3] W absmax, [4] X-lo, [5] attn-lo

// GEMM operands: A = hi fp16 + lo int8 (scaled); B = hi fp16 + full int8.
__device__ __half  g_xhi[(size_t)M_ * HID_];
__device__ int8_t  g_xl8[(size_t)M_ * HID_];
__device__ __half  g_lo16[(size_t)M_ * HID_];      // attn-out lo staging (fp16)
__device__ __half  g_bhi[(size_t)4 * HID_ * HID_];
__device__ int8_t  g_bq8[(size_t)4 * HID_ * HID_];

// fp16 attention operands [b,h,s,d]: Q split hi/lo; K, V hi only.
#define QKV_ELEMS ((size_t)B_ * H_ * S_ * D_)
__device__ __half g_qh[QKV_ELEMS];
__device__ __half g_ql[QKV_ELEMS];
__device__ __half g_kh[QKV_ELEMS];
__device__ __half g_vh[QKV_ELEMS];

// ---------------------------------------------------------------------------
// PTX helpers (non-'a' features only)
// ---------------------------------------------------------------------------
__device__ __forceinline__ uint32_t smem_u32(const void* p) {
    uint32_t a;
    asm("{ .reg .u64 t; cvta.to.shared.u64 t, %1; cvt.u32.u64 %0, t; }"
        : "=r"(a) : "l"(p));
    return a;
}
__device__ __forceinline__ void cpa16(uint32_t s, const void* g) {
    asm volatile("cp.async.cg.shared.global [%0], [%1], 16;" :: "r"(s), "l"(g));
}
#define CP_COMMIT() asm volatile("cp.async.commit_group;" ::: "memory")
#define CP_WAIT0()  asm volatile("cp.async.wait_group 0;" ::: "memory")
#define CP_WAIT1()  asm volatile("cp.async.wait_group 1;" ::: "memory")

#define LDSM4(r, addr)                                                        \
    asm volatile("ldmatrix.sync.aligned.m8n8.x4.shared.b16 {%0,%1,%2,%3}, [%4];" \
                 : "=r"((r)[0]), "=r"((r)[1]), "=r"((r)[2]), "=r"((r)[3])     \
                 : "r"(addr))
#define LDSM4T(r, addr)                                                       \
    asm volatile("ldmatrix.sync.aligned.m8n8.x4.trans.shared.b16 {%0,%1,%2,%3}, [%4];" \
                 : "=r"((r)[0]), "=r"((r)[1]), "=r"((r)[2]), "=r"((r)[3])     \
                 : "r"(addr))

#define MMAF32(d, a, b)                                                       \
    asm volatile(                                                             \
        "mma.sync.aligned.m16n8k16.row.col.f32.f16.f16.f32 "                  \
        "{%0,%1,%2,%3}, {%4,%5,%6,%7}, {%8,%9}, {%0,%1,%2,%3};"               \
        : "+f"((d)[0]), "+f"((d)[1]), "+f"((d)[2]), "+f"((d)[3])              \
        : "r"((a)[0]), "r"((a)[1]), "r"((a)[2]), "r"((a)[3]),                 \
          "r"((b)[0]), "r"((b)[1]))

#define IMMA(d, a, b)                                                         \
    asm volatile(                                                             \
        "mma.sync.aligned.m16n8k32.row.col.s32.s8.s8.s32 "                    \
        "{%0,%1,%2,%3}, {%4,%5,%6,%7}, {%8,%9}, {%0,%1,%2,%3};"               \
        : "+r"((d)[0]), "+r"((d)[1]), "+r"((d)[2]), "+r"((d)[3])              \
        : "r"((a)[0]), "r"((a)[1]), "r"((a)[2]), "r"((a)[3]),                 \
          "r"((b)[0]), "r"((b)[1]))

__device__ __forceinline__ float2 h2f2(uint32_t u) {
    __half2 h = *(__half2*)&u;
    return __half22float2(h);
}
__device__ __forceinline__ uint32_t f2h2(float x, float y) {
    __half2 h = __float22half2_rn(make_float2(x, y));
    return *(uint32_t*)&h;
}
__device__ __forceinline__ void atomicMaxF(float* addr, float v) {
    atomicMax((int*)addr, __float_as_int(v));   // valid: v >= 0, init 0
}
__device__ __forceinline__ int q8i(float x, float inv) {
    int v = __float2int_rn(x * inv);
    return max(-127, min(127, v));
}

// ---------------------------------------------------------------------------
// fp32 -> fp16 hi / residual
// ---------------------------------------------------------------------------
__device__ __forceinline__ void split1(float x, unsigned short& h, float& lo) {
    __half hb = __float2half_rn(x);
    h = __half_as_ushort(hb);
    lo = x - __half2float(hb);
}

// absmax: LO=0 -> max|x|, LO=1 -> max|x - fp16(x)|
template <int LO>
__global__ void absmax_kernel(const float* __restrict__ src, int n4, int sidx) {
    float m = 0.f;
    for (int i = blockIdx.x * blockDim.x + threadIdx.x; i < n4;
         i += gridDim.x * blockDim.x) {
        float4 v = ((const float4*)src)[i];
        float a, b, c, d;
        if (LO) {
            a = fabsf(v.x - __half2float(__float2half_rn(v.x)));
            b = fabsf(v.y - __half2float(__float2half_rn(v.y)));
            c = fabsf(v.z - __half2float(__float2half_rn(v.z)));
            d = fabsf(v.w - __half2float(__float2half_rn(v.w)));
        } else {
            a = fabsf(v.x); b = fabsf(v.y); c = fabsf(v.z); d = fabsf(v.w);
        }
        m = fmaxf(m, fmaxf(fmaxf(a, b), fmaxf(c, d)));
    }
#pragma unroll
    for (int o = 16; o; o >>= 1) m = fmaxf(m, __shfl_xor_sync(0xffffffffu, m, o));
    if ((threadIdx.x & 31) == 0) atomicMaxF(&g_scl[sidx], m);
}

__global__ void zscl_kernel() {
    if (threadIdx.x < 8) g_scl[threadIdx.x] = 0.f;
}

// Activations: X [M,K] fp32 -> g_xhi fp16 + g_xl8 int8 (scale g_scl[4])
__global__ void asplit_kernel(const float* __restrict__ src) {
    size_t i = (size_t)blockIdx.x * 256 + threadIdx.x;
    const float inv = 127.f / fmaxf(g_scl[4], 1e-20f);
    float4 v = ((const float4*)src)[i];
    ushort4 h;
    float l0, l1, l2, l3;
    split1(v.x, h.x, l0);
    split1(v.y, h.y, l1);
    split1(v.z, h.z, l2);
    split1(v.w, h.w, l3);
    ((ushort4*)g_xhi)[i] = h;
    uint32_t p = (uint32_t)(q8i(l0, inv) & 0xff) |
                 ((uint32_t)(q8i(l1, inv) & 0xff) << 8) |
                 ((uint32_t)(q8i(l2, inv) & 0xff) << 16) |
                 ((uint32_t)(q8i(l3, inv) & 0xff) << 24);
    ((uint32_t*)g_xl8)[i] = p;
}

// Weights: W [K,N] fp32 -> slot widx: [N,K] fp16 hi + [N,K] int8 full
__global__ void wsplit_kernel(const float* __restrict__ W, int widx) {
    __shared__ float ts[32][33];
    const int tx = threadIdx.x, ty = threadIdx.y;
    const int n0 = blockIdx.x * 32, k0 = blockIdx.y * 32;
    __half* bh = g_bhi + (size_t)widx * HID_ * HID_;
    int8_t* bq = g_bq8 + (size_t)widx * HID_ * HID_;
    const float inv = 127.f / fmaxf(g_scl[widx], 1e-20f);
#pragma unroll
    for (int i = 0; i < 4; i++)
        ts[ty + 8 * i][tx] = W[(size_t)(k0 + ty + 8 * i) * HID_ + n0 + tx];
    __syncthreads();
#pragma unroll
    for (int i = 0; i < 4; i++) {
        int n = n0 + ty + 8 * i;
        int k = k0 + tx;
        float v = ts[tx][ty + 8 * i];
        bh[(size_t)n * HID_ + k] = __float2half_rn(v);
        bq[(size_t)n * HID_ + k] = (int8_t)q8i(v, inv);
    }
}

// attn-out lo fp16 -> int8 (scale g_scl[5])
__global__ void aquant_kernel() {
    size_t i = (size_t)blockIdx.x * 256 + threadIdx.x;   // groups of 4
    const float inv = 127.f / fmaxf(g_scl[5], 1e-20f);
    uint2 u = ((const uint2*)g_lo16)[i];
    float2 f0 = h2f2(u.x), f1 = h2f2(u.y);
    uint32_t p = (uint32_t)(q8i(f0.x, inv) & 0xff) |
                 ((uint32_t)(q8i(f0.y, inv) & 0xff) << 8) |
                 ((uint32_t)(q8i(f1.x, inv) & 0xff) << 16) |
                 ((uint32_t)(q8i(f1.y, inv) & 0xff) << 24);
    ((uint32_t*)g_xl8)[i] = p;
}

// ---------------------------------------------------------------------------
// GEMM: main term fp16 (Ah*Bh, f32-accum) + int8 k32 correction (Al_q*B_q).
// 3-stage cp.async pipeline. MODE==1: fused QKV. MODE==0: O projection.
// ---------------------------------------------------------------------------
#define PITCH  144
#define PITCH8 80
#define AIB (128 * PITCH)                 // 18432: A int8
#define BHB (AIB + 128 * PITCH8)          // 28672: B fp16
#define BIB (BHB + 128 * PITCH)           // 47104: B int8
#define BUFB (BIB + 128 * PITCH8)         // 57344
#define GEMM_SMEM (3 * BUFB)              // 172032
#define NCH (HID_ / 64)                   // 32

template <int MODE>
__global__ __launch_bounds__(256, 1) void mma_gemm(float* __restrict__ Cout) {
    extern __shared__ char dsm[];
    const uint32_t sb = smem_u32(dsm);
    const int t = threadIdx.x;
    const int lane = t & 31, wid = t >> 5;
    const int wm = wid & 3, wn = wid >> 2;
    const int m0 = blockIdx.y * 128;
    const int widx = (MODE == 1) ? (blockIdx.x >> 4) : 3;
    const int nblk = (MODE == 1) ? (blockIdx.x & 15) : blockIdx.x;
    const int n0 = nblk * 128;

    const __half* __restrict__ AH = g_xhi;
    const int8_t* __restrict__ AI = g_xl8;
    const __half* __restrict__ BH = g_bhi + (size_t)widx * HID_ * HID_;
    const int8_t* __restrict__ BI = g_bq8 + (size_t)widx * HID_ * HID_;
    const float cf = g_scl[(MODE == 1) ? 4 : 5] * g_scl[widx] *
                     (1.f / (127.f * 127.f));

    float acc[2][8][4];
    int accI[2][8][4];
#pragma unroll
    for (int i = 0; i < 2; i++)
#pragma unroll
        for (int j = 0; j < 8; j++)
#pragma unroll
            for (int k = 0; k < 4; k++) {
                acc[i][j][k] = 0.f;
                accI[i][j][k] = 0;
            }

    // prologue: stages 0,1
#pragma unroll
    for (int s = 0; s < 2; s++) {
        const uint32_t base = sb + s * BUFB;
        const int k0 = s * 64;
#pragma unroll
        for (int j = 0; j < 4; j++) {
            int c = t + j * 256, row = c >> 3, seg = c & 7;
            cpa16(base + row * PITCH + seg * 16,
                  AH + (size_t)(m0 + row) * HID_ + k0 + seg * 8);
            cpa16(base + BHB + row * PITCH + seg * 16,
                  BH + (size_t)(n0 + row) * HID_ + k0 + seg * 8);
        }
#pragma unroll
        for (int j = 0; j < 2; j++) {
            int c = t + j * 256, row = c >> 2, seg = c & 3;
            cpa16(base + AIB + row * PITCH8 + seg * 16,
                  AI + (size_t)(m0 + row) * HID_ + k0 + seg * 16);
            cpa16(base + BIB + row * PITCH8 + seg * 16,
                  BI + (size_t)(n0 + row) * HID_ + k0 + seg * 16);
        }
        CP_COMMIT();
    }

    const uint32_t lm_a_off =
        (uint32_t)((wm * 32 + (lane & 15)) * PITCH + (lane >> 4) * 16);
    const uint32_t lm_b_off =
        (uint32_t)((wn * 64 + (lane & 15)) * PITCH + (lane >> 4) * 16);
    const uint32_t lm_ai_off =
        (uint32_t)((wm * 32 + (lane & 15)) * PITCH8 + (lane >> 4) * 16);
    const uint32_t lm_bi_off =
        (uint32_t)((wn * 64 + (lane & 15)) * PITCH8 + (lane >> 4) * 16);

    int bufn = 0;
    int pbuf = 2;
    for (int c = 0; c < NCH; c++) {
        CP_WAIT1();
        __syncthreads();

        if (c + 2 < NCH) {
            const uint32_t base = sb + pbuf * BUFB;
            const int k0 = (c + 2) * 64;
#pragma unroll
            for (int j = 0; j < 4; j++) {
                int cc = t + j * 256, row = cc >> 3, seg = cc & 7;
                cpa16(base + row * PITCH + seg * 16,
                      AH + (size_t)(m0 + row) * HID_ + k0 + seg * 8);
                cpa16(base + BHB + row * PITCH + seg * 16,
                      BH + (size_t)(n0 + row) * HID_ + k0 + seg * 8);
            }
#pragma unroll
            for (int j = 0; j < 2; j++) {
                int cc = t + j * 256, row = cc >> 2, seg = cc & 3;
                cpa16(base + AIB + row * PITCH8 + seg * 16,
                      AI + (size_t)(m0 + row) * HID_ + k0 + seg * 16);
                cpa16(base + BIB + row * PITCH8 + seg * 16,
                      BI + (size_t)(n0 + row) * HID_ + k0 + seg * 16);
            }
        }
        CP_COMMIT();

        const uint32_t cb = sb + bufn * BUFB;
#pragma unroll
        for (int s2 = 0; s2 < 2; s2++) {
            // ---- fp16 main term: two k16 substeps ----
#pragma unroll
            for (int kk = 0; kk < 2; kk++) {
                const int ks = s2 * 2 + kk;
                uint32_t ah[2][4];
#pragma unroll
                for (int mt = 0; mt < 2; mt++)
                    LDSM4(ah[mt], cb + lm_a_off + mt * (16 * PITCH) + ks * 32);
                uint32_t bh[8][2];
#pragma unroll
                for (int np = 0; np < 4; np++) {
                    uint32_t r[4];
                    LDSM4(r, cb + BHB + lm_b_off + np * (16 * PITCH) + ks * 32);
                    bh[2 * np][0] = r[0]; bh[2 * np + 1][0] = r[1];
                    bh[2 * np][1] = r[2]; bh[2 * np + 1][1] = r[3];
                }
#pragma unroll
                for (int mt = 0; mt < 2; mt++)
#pragma unroll
                    for (int nt = 0; nt < 8; nt++)
                        MMAF32(acc[mt][nt], ah[mt], bh[nt]);
            }
            // ---- int8 correction: one k32 step ----
            uint32_t aI[2][4];
#pragma unroll
            for (int mt = 0; mt < 2; mt++)
                LDSM4(aI[mt], cb + AIB + lm_ai_off + mt * (16 * PITCH8) + s2 * 32);
#pragma unroll
            for (int np = 0; np < 4; np++) {
                uint32_t r[4];
                LDSM4(r, cb + BIB + lm_bi_off + np * (16 * PITCH8) + s2 * 32);
                uint32_t b0[2] = {r[0], r[2]}, b1[2] = {r[1], r[3]};
#pragma unroll
                for (int mt = 0; mt < 2; mt++) {
                    IMMA(accI[mt][2 * np], aI[mt], b0);
                    IMMA(accI[mt][2 * np + 1], aI[mt], b1);
                }
            }
        }
        bufn = (bufn == 2) ? 0 : bufn + 1;
        pbuf = (pbuf == 2) ? 0 : pbuf + 1;
    }

    // Epilogue: merge int8 correction, then write
    const int qrow = lane >> 2;
    const int qcol = (lane & 3) * 2;
#pragma unroll
    for (int mt = 0; mt < 2; mt++) {
#pragma unroll
        for (int nt = 0; nt < 8; nt++)
#pragma unroll
            for (int e = 0; e < 4; e++)
                acc[mt][nt][e] += (float)accI[mt][nt][e] * cf;
#pragma unroll
        for (int half_ = 0; half_ < 2; half_++) {
            const int m = m0 + wm * 32 + mt * 16 + qrow + half_ * 8;
            if (MODE == 1 && widx == 2) {
                int b_ = m >> 11, s_ = m & (S_ - 1);
                size_t base = (((size_t)b_ * H_ + nblk) * S_ + s_) * D_;
#pragma unroll
                for (int nt = 0; nt < 8; nt++) {
                    int col = wn * 64 + nt * 8 + qcol;
                    *(uint32_t*)(g_vh + base + col) =
                        f2h2(acc[mt][nt][half_ * 2], acc[mt][nt][half_ * 2 + 1]);
                }
            } else {
                float* dst;
                size_t base;
                if (MODE == 0) {
                    dst = Cout;
                    base = (size_t)m * HID_ + n0;
                } else {
                    int b_ = m >> 11, s_ = m & (S_ - 1);
                    dst = (widx == 0) ? g_q : g_k;
                    base = (((size_t)b_ * H_ + nblk) * S_ + s_) * D_;
                }
#pragma unroll
                for (int nt = 0; nt < 8; nt++) {
                    int col = wn * 64 + nt * 8 + qcol;
                    *(float2*)(dst + base + col) =
                        make_float2(acc[mt][nt][half_ * 2], acc[mt][nt][half_ * 2 + 1]);
                }
            }
        }
    }
}

// ---------------------------------------------------------------------------
// RoPE: read fp32 g_q/g_k, rotate, emit qh/ql (fp16 split) and kh (round).
// ---------------------------------------------------------------------------
__global__ void rope_split_kernel(const float* __restrict__ cosb,
                                  const float* __restrict__ sinb) {
    int tid = blockIdx.x * 256 + threadIdx.x;
    int d = tid & 63;
    int s = (tid >> 6) & (S_ - 1);
    int bh = tid >> 17;
    size_t base = ((size_t)bh * S_ + s) * D_;
    float c0 = cosb[s * D_ + d], c1 = cosb[s * D_ + d + 64];
    float s0 = sinb[s * D_ + d], s1 = sinb[s * D_ + d + 64];

    float q0 = g_q[base + d], q1 = g_q[base + d + 64];
    float k0 = g_k[base + d], k1 = g_k[base + d + 64];
    float qa = q0 * c0 - q1 * s0;
    float qb = q1 * c1 + q0 * s1;
    float ka = k0 * c0 - k1 * s0;
    float kb = k1 * c1 + k0 * s1;

    unsigned short h;
    float lo;
    split1(qa, h, lo);
    g_qh[base + d] = __ushort_as_half(h);
    g_ql[base + d] = __float2half_rn(lo);
    split1(qb, h, lo);
    g_qh[base + d + 64] = __ushort_as_half(h);
    g_ql[base + d + 64] = __float2half_rn(lo);
    g_kh[base + d] = __float2half_rn(ka);
    g_kh[base + d + 64] = __float2half_rn(kb);
}

// ---------------------------------------------------------------------------
// Flash attention, fp16x2 mma (unchanged from R7 core). Epilogue: hi fp16 to
// g_xhi, lo fp16 to g_lo16, and absmax(lo) -> g_scl[5].
// ---------------------------------------------------------------------------
#define AP   272
#define AMAT (128 * AP)
#define ATTN_SMEM (4 * AMAT)          // 139264

__global__ __launch_bounds__(256, 1) void attn_mma_kernel() {
    extern __shared__ char sm8[];
    const uint32_t sb = smem_u32(sm8);
    const uint32_t Qh = sb,            Ql = sb + AMAT;
    const uint32_t Kh = sb + 2 * AMAT, Vh = sb + 3 * AMAT;

    const int t = threadIdx.x, lane = t & 31, wid = t >> 5;
    const int bh = blockIdx.y;
    const int q0 = blockIdx.x * 128;
    const size_t qoff = ((size_t)bh * S_ + q0) * D_;
    const size_t koff = (size_t)bh * S_ * D_;

#pragma unroll
    for (int j = 0; j < 8; j++) {
        int idx = t + j * 256;
        int row = idx >> 4, ch = idx & 15;
        uint32_t so = (uint32_t)(row * AP + ch * 16);
        size_t go = qoff + (size_t)row * D_ + ch * 8;
        cpa16(Qh + so, g_qh + go);
        cpa16(Ql + so, g_ql + go);
    }
    CP_COMMIT();

    float sa[16][4];
    float oa[16][4];
#pragma unroll
    for (int i = 0; i < 16; i++)
#pragma unroll
        for (int j = 0; j < 4; j++) oa[i][j] = 0.f;
    float m0r = -1e30f, m1r = -1e30f, l0r = 0.f, l1r = 0.f;

    const float scale = 0.088388347648318447f;
    const uint32_t a_off =
        (uint32_t)((wid * 16 + (lane & 15)) * AP + (lane >> 4) * 16);
    const uint32_t lm_lo = (uint32_t)((lane & 15) * AP + (lane >> 4) * 16);

    for (int kt = 0; kt < S_ / 128; kt++) {
        __syncthreads();
#pragma unroll
        for (int j = 0; j < 8; j++) {
            int idx = t + j * 256;
            int row = idx >> 4, ch = idx & 15;
            uint32_t so = (uint32_t)(row * AP + ch * 16);
            size_t go = koff + (size_t)(kt * 128 + row) * D_ + ch * 8;
            cpa16(Kh + so, g_kh + go);
        }
        CP_COMMIT();
#pragma unroll
        for (int j = 0; j < 8; j++) {
            int idx = t + j * 256;
            int row = idx >> 4, ch = idx & 15;
            uint32_t so = (uint32_t)(row * AP + ch * 16);
            size_t go = koff + (size_t)(kt * 128 + row) * D_ + ch * 8;
            cpa16(Vh + so, g_vh + go);
        }
        CP_COMMIT();

        CP_WAIT1();
        __syncthreads();

#pragma unroll
        for (int i = 0; i < 16; i++)
#pragma unroll
            for (int j = 0; j < 4; j++) sa[i][j] = 0.f;

#pragma unroll
        for (int ks = 0; ks < 8; ks++) {
            uint32_t qh[4], ql[4];
            LDSM4(qh, Qh + a_off + ks * 32);
            LDSM4(ql, Ql + a_off + ks * 32);
#pragma unroll
            for (int np = 0; np < 8; np++) {
                uint32_t boff = lm_lo + (uint32_t)(np * 16 * AP) + ks * 32;
                uint32_t r[4], kh0[2], kh1[2];
                LDSM4(r, Kh + boff);
                kh0[0] = r[0]; kh1[0] = r[1]; kh0[1] = r[2]; kh1[1] = r[3];
                MMAF32(sa[2 * np], qh, kh0);
                MMAF32(sa[2 * np], ql, kh0);
                MMAF32(sa[2 * np + 1], qh, kh1);
                MMAF32(sa[2 * np + 1], ql, kh1);
            }
        }

        float rm0 = -1e30f, rm1 = -1e30f;
#pragma unroll
        for (int nt = 0; nt < 16; nt++) {
            rm0 = fmaxf(rm0, fmaxf(sa[nt][0], sa[nt][1]));
            rm1 = fmaxf(rm1, fmaxf(sa[nt][2], sa[nt][3]));
        }
#pragma unroll
        for (int off = 1; off <= 2; off <<= 1) {
            rm0 = fmaxf(rm0, __shfl_xor_sync(0xffffffffu, rm0, off));
            rm1 = fmaxf(rm1, __shfl_xor_sync(0xffffffffu, rm1, off));
        }
        float mn0 = fmaxf(m0r, rm0 * scale);
        float mn1 = fmaxf(m1r, rm1 * scale);
        float al0 = __expf(m0r - mn0);
        float al1 = __expf(m1r - mn1);
        m0r = mn0;
        m1r = mn1;
        float rs0 = 0.f, rs1 = 0.f;
#pragma unroll
        for (int nt = 0; nt < 16; nt++) {
            float p0 = __expf(fmaf(sa[nt][0], scale, -mn0));
            float p1 = __expf(fmaf(sa[nt][1], scale, -mn0));
            float p2 = __expf(fmaf(sa[nt][2], scale, -mn1));
            float p3 = __expf(fmaf(sa[nt][3], scale, -mn1));
            sa[nt][0] = p0; sa[nt][1] = p1; sa[nt][2] = p2; sa[nt][3] = p3;
            rs0 += p0 + p1;
            rs1 += p2 + p3;
        }
#pragma unroll
        for (int off = 1; off <= 2; off <<= 1) {
            rs0 += __shfl_xor_sync(0xffffffffu, rs0, off);
            rs1 += __shfl_xor_sync(0xffffffffu, rs1, off);
        }
        l0r = l0r * al0 + rs0;
        l1r = l1r * al1 + rs1;
#pragma unroll
        for (int nt = 0; nt < 16; nt++) {
            oa[nt][0] *= al0;
            oa[nt][1] *= al0;
            oa[nt][2] *= al1;
            oa[nt][3] *= al1;
        }

        CP_WAIT0();
        __syncthreads();

#pragma unroll
        for (int ks = 0; ks < 8; ks++) {
            uint32_t aH[4], aL[4];
#pragma unroll
            for (int g = 0; g < 2; g++) {
                const int tt = 2 * ks + g;
                float x0 = sa[tt][0], y0 = sa[tt][1];
                float x1 = sa[tt][2], y1 = sa[tt][3];
                uint32_t h0 = f2h2(x0, y0);
                uint32_t h1 = f2h2(x1, y1);
                float2 b0 = h2f2(h0);
                float2 b1 = h2f2(h1);
                aH[2 * g]     = h0;
                aH[2 * g + 1] = h1;
                aL[2 * g]     = f2h2(x0 - b0.x, y0 - b0.y);
                aL[2 * g + 1] = f2h2(x1 - b1.x, y1 - b1.y);
            }
            const uint32_t vbase = lm_lo + (uint32_t)(ks * 16 * AP);
#pragma unroll
            for (int np = 0; np < 8; np++) {
                uint32_t r[4], vh0[2], vh1[2];
                LDSM4T(r, Vh + vbase + np * 32);
                vh0[0] = r[0]; vh0[1] = r[1]; vh1[0] = r[2]; vh1[1] = r[3];
                MMAF32(oa[2 * np], aH, vh0);
                MMAF32(oa[2 * np], aL, vh0);
                MMAF32(oa[2 * np + 1], aH, vh1);
                MMAF32(oa[2 * np + 1], aL, vh1);
            }
        }
    }

    // ---- finalize: hi -> g_xhi, lo -> g_lo16, absmax(lo) -> g_scl[5] ----
    const int b_ = bh >> 4, h = bh & 15;
    const int row0 = q0 + wid * 16 + (lane >> 2);
    const float inv0 = 1.0f / l0r, inv1 = 1.0f / l1r;
    const size_t base0 = ((size_t)b_ * S_ + row0) * HID_ + h * D_;
    const size_t base1 = ((size_t)b_ * S_ + row0 + 8) * HID_ + h * D_;
    const int col0 = (lane & 3) * 2;
    float mx = 0.f;
#pragma unroll
    for (int nt = 0; nt < 16; nt++) {
        int col = 8 * nt + col0;
        float x0 = oa[nt][0] * inv0, y0 = oa[nt][1] * inv0;
        float x1 = oa[nt][2] * inv1, y1 = oa[nt][3] * inv1;
        uint32_t h0 = f2h2(x0, y0);
        uint32_t h1 = f2h2(x1, y1);
        float2 r0 = h2f2(h0), r1 = h2f2(h1);
        float lx0 = x0 - r0.x, ly0 = y0 - r0.y;
        float lx1 = x1 - r1.x, ly1 = y1 - r1.y;
        *(uint32_t*)(g_xhi + base0 + col) = h0;
        *(uint32_t*)(g_xhi + base1 + col) = h1;
        *(uint32_t*)(g_lo16 + base0 + col) = f2h2(lx0, ly0);
        *(uint32_t*)(g_lo16 + base1 + col) = f2h2(lx1, ly1);
        mx = fmaxf(mx, fmaxf(fmaxf(fabsf(lx0), fabsf(ly0)),
                             fmaxf(fabsf(lx1), fabsf(ly1))));
    }
#pragma unroll
    for (int o = 16; o; o >>= 1) mx = fmaxf(mx, __shfl_xor_sync(0xffffffffu, mx, o));
    if (lane == 0) atomicMaxF(&g_scl[5], mx);
}

// ---------------------------------------------------------------------------
// Launch
// ---------------------------------------------------------------------------
extern "C" void kernel_launch(void* const* d_in, const int* in_sizes, int n_in,
                              void* d_out, int out_size) {
    const float* X = (const float*)d_in[0];
    const float* cosb = (const float*)d_in[1];
    const float* sinb = (const float*)d_in[2];
    const float* Wq = (const float*)d_in[3];
    const float* Wk = (const float*)d_in[4];
    const float* Wv = (const float*)d_in[5];
    const float* Wo = (const float*)d_in[6];
    float* out = (float*)d_out;

    cudaFuncSetAttribute(mma_gemm<0>, cudaFuncAttributeMaxDynamicSharedMemorySize, GEMM_SMEM);
    cudaFuncSetAttribute(mma_gemm<1>, cudaFuncAttributeMaxDynamicSharedMemorySize, GEMM_SMEM);
    cudaFuncSetAttribute(attn_mma_kernel, cudaFuncAttributeMaxDynamicSharedMemorySize, ATTN_SMEM);

    const dim3 wgrid(64, 64);
    const dim3 wblk(32, 8);
    const int WN4 = HID_ * HID_ / 4;
    const int XN4 = M_ * HID_ / 4;

    zscl_kernel<<<1, 32>>>();
    absmax_kernel<0><<<1024, 256>>>(Wq, WN4, 0);
    absmax_kernel<0><<<1024, 256>>>(Wk, WN4, 1);
    absmax_kernel<0><<<1024, 256>>>(Wv, WN4, 2);
    absmax_kernel<0><<<1024, 256>>>(Wo, WN4, 3);
    absmax_kernel<1><<<1024, 256>>>(X, XN4, 4);

    wsplit_kernel<<<wgrid, wblk>>>(Wq, 0);
    wsplit_kernel<<<wgrid, wblk>>>(Wk, 1);
    wsplit_kernel<<<wgrid, wblk>>>(Wv, 2);
    wsplit_kernel<<<wgrid, wblk>>>(Wo, 3);
    asplit_kernel<<<XN4 / 256, 256>>>(X);

    // fused QKV projection
    mma_gemm<1><<<dim3(48, M_ / 128), 256, GEMM_SMEM>>>(nullptr);

    rope_split_kernel<<<(B_ * H_ * S_ * 64) / 256, 256>>>(cosb, sinb);

    // attention writes g_xhi (hi) + g_lo16 (lo) + g_scl[5]
    attn_mma_kernel<<<dim3(S_ / 128, B_ * H_), 256, ATTN_SMEM>>>();

    // quantize attn-out lo to int8, then O projection
    aquant_kernel<<<XN4 / 256, 256>>>();
    mma_gemm<0><<<dim3(HID_ / 128, M_ / 128), 256, GEMM_SMEM>>>(out);
}

// round 9
// speedup vs baseline: 1.5318x; 1.5318x over previous
#include <cuda_runtime.h>
#include <cuda_fp16.h>
#include <cstdint>

// ---------------------------------------------------------------------------
// Problem constants
// ---------------------------------------------------------------------------
#define B_ 2
#define S_ 2048
#define H_ 16
#define D_ 128
#define HID_ 2048
#define M_ (B_ * S_)   // 4096

// fp16 buffers. Activations split hi/lo; weights hi only (2-term emulation).
__device__ __half g_xhi[(size_t)M_ * HID_];
__device__ __half g_xlo[(size_t)M_ * HID_];
__device__ __half g_bhi[(size_t)4 * HID_ * HID_];

// fp16 attention operands [b,h,s,d]: Q split hi/lo; K, V hi only.
#define QKV_ELEMS ((size_t)B_ * H_ * S_ * D_)
__device__ __half g_qh[QKV_ELEMS];
__device__ __half g_ql[QKV_ELEMS];
__device__ __half g_kh[QKV_ELEMS];
__device__ __half g_vh[QKV_ELEMS];

// ---------------------------------------------------------------------------
// PTX helpers (non-'a' features only)
// ---------------------------------------------------------------------------
__device__ __forceinline__ uint32_t smem_u32(const void* p) {
    uint32_t a;
    asm("{ .reg .u64 t; cvta.to.shared.u64 t, %1; cvt.u32.u64 %0, t; }"
        : "=r"(a) : "l"(p));
    return a;
}
__device__ __forceinline__ void cpa16(uint32_t s, const void* g) {
    asm volatile("cp.async.cg.shared.global [%0], [%1], 16;" :: "r"(s), "l"(g));
}
#define CP_COMMIT() asm volatile("cp.async.commit_group;" ::: "memory")
#define CP_WAIT0()  asm volatile("cp.async.wait_group 0;" ::: "memory")
#define CP_WAIT1()  asm volatile("cp.async.wait_group 1;" ::: "memory")

#define LDSM4(r, addr)                                                        \
    asm volatile("ldmatrix.sync.aligned.m8n8.x4.shared.b16 {%0,%1,%2,%3}, [%4];" \
                 : "=r"((r)[0]), "=r"((r)[1]), "=r"((r)[2]), "=r"((r)[3])     \
                 : "r"(addr))
#define LDSM4T(r, addr)                                                       \
    asm volatile("ldmatrix.sync.aligned.m8n8.x4.trans.shared.b16 {%0,%1,%2,%3}, [%4];" \
                 : "=r"((r)[0]), "=r"((r)[1]), "=r"((r)[2]), "=r"((r)[3])     \
                 : "r"(addr))

#define MMAF32(d, a, b)                                                       \
    asm volatile(                                                             \
        "mma.sync.aligned.m16n8k16.row.col.f32.f16.f16.f32 "                  \
        "{%0,%1,%2,%3}, {%4,%5,%6,%7}, {%8,%9}, {%0,%1,%2,%3};"               \
        : "+f"((d)[0]), "+f"((d)[1]), "+f"((d)[2]), "+f"((d)[3])              \
        : "r"((a)[0]), "r"((a)[1]), "r"((a)[2]), "r"((a)[3]),                 \
          "r"((b)[0]), "r"((b)[1]))

__device__ __forceinline__ float2 h2f2(uint32_t u) {
    __half2 h = *(__half2*)&u;
    return __half22float2(h);
}
__device__ __forceinline__ uint32_t f2h2(float x, float y) {
    __half2 h = __float22half2_rn(make_float2(x, y));
    return *(uint32_t*)&h;
}

// fp32 -> fp16 hi/lo split
__device__ __forceinline__ void split1(float x, unsigned short& h, unsigned short& l) {
    __half hb = __float2half_rn(x);
    __half lb = __float2half_rn(x - __half2float(hb));
    h = __half_as_ushort(hb);
    l = __half_as_ushort(lb);
}

// ---------------------------------------------------------------------------
// Activations: X [M,K] fp32 -> g_xhi/g_xlo fp16.
// ---------------------------------------------------------------------------
__global__ void asplit_kernel(const float* __restrict__ src) {
    size_t i = (size_t)blockIdx.x * 256 + threadIdx.x;
    float4 v = ((const float4*)src)[i];
    ushort4 h, l;
    split1(v.x, h.x, l.x);
    split1(v.y, h.y, l.y);
    split1(v.z, h.z, l.z);
    split1(v.w, h.w, l.w);
    ((ushort4*)g_xhi)[i] = h;
    ((ushort4*)g_xlo)[i] = l;
}

// All 4 weights in one launch: W [K,N] fp32 -> g_bhi slot z, [N,K] fp16 hi.
__global__ void wsplit_kernel(const float* __restrict__ W0,
                              const float* __restrict__ W1,
                              const float* __restrict__ W2,
                              const float* __restrict__ W3) {
    __shared__ float ts[32][33];
    const int tx = threadIdx.x, ty = threadIdx.y;
    const int n0 = blockIdx.x * 32, k0 = blockIdx.y * 32;
    const int widx = blockIdx.z;
    const float* W = (widx == 0) ? W0 : (widx == 1) ? W1 : (widx == 2) ? W2 : W3;
    __half* bh = g_bhi + (size_t)widx * HID_ * HID_;
#pragma unroll
    for (int i = 0; i < 4; i++)
        ts[ty + 8 * i][tx] = W[(size_t)(k0 + ty + 8 * i) * HID_ + n0 + tx];
    __syncthreads();
#pragma unroll
    for (int i = 0; i < 4; i++) {
        int n = n0 + ty + 8 * i;
        int k = k0 + tx;
        bh[(size_t)n * HID_ + k] = __float2half_rn(ts[tx][ty + 8 * i]);
    }
}

// ---------------------------------------------------------------------------
// mma.sync fp16x2 GEMM (Ah*Bh + Al*Bh, both f32-accum), 3-stage pipeline.
// MODE==1: fused QKV (blockIdx.x = widx*16 + head).
//   widx 0: RoPE in epilogue -> g_qh/g_ql fp16
//   widx 1: RoPE in epilogue -> g_kh fp16
//   widx 2: -> g_vh fp16
// MODE==0: O projection -> Cout fp32 row-major.
// ---------------------------------------------------------------------------
#define PITCH 144
#define MATB  (128 * PITCH)          // 18432
#define BUFB  (3 * MATB)             // 55296 (Ah, Al, Bh)
#define GEMM_SMEM (3 * BUFB)         // 165888
#define NCH (HID_ / 64)              // 32

template <int MODE>
__global__ __launch_bounds__(256, 1) void mma_gemm(float* __restrict__ Cout,
                                                   const float* __restrict__ cosb,
                                                   const float* __restrict__ sinb) {
    extern __shared__ char dsm[];
    const uint32_t sb = smem_u32(dsm);
    const int t = threadIdx.x;
    const int lane = t & 31, wid = t >> 5;
    const int wm = wid & 3, wn = wid >> 2;
    const int m0 = blockIdx.y * 128;
    const int widx = (MODE == 1) ? (blockIdx.x >> 4) : 3;
    const int nblk = (MODE == 1) ? (blockIdx.x & 15) : blockIdx.x;
    const int n0 = nblk * 128;

    const __half* __restrict__ AH = g_xhi;
    const __half* __restrict__ AL = g_xlo;
    const __half* __restrict__ BH = g_bhi + (size_t)widx * HID_ * HID_;

    float acc[2][8][4];
#pragma unroll
    for (int i = 0; i < 2; i++)
#pragma unroll
        for (int j = 0; j < 8; j++)
#pragma unroll
            for (int k = 0; k < 4; k++) acc[i][j][k] = 0.f;

    const int lrow = t >> 3;
    const int lch = t & 7;

#pragma unroll
    for (int s = 0; s < 2; s++) {
        const uint32_t base = sb + s * BUFB;
        const int k0 = s * 64;
#pragma unroll
        for (int j = 0; j < 4; j++) {
            int row = lrow + j * 32;
            uint32_t sa = base + row * PITCH + lch * 16;
            size_t ga = (size_t)(m0 + row) * HID_ + k0 + lch * 8;
            size_t gb = (size_t)(n0 + row) * HID_ + k0 + lch * 8;
            cpa16(sa, AH + ga);
            cpa16(sa + MATB, AL + ga);
            cpa16(sa + 2 * MATB, BH + gb);
        }
        CP_COMMIT();
    }

    const uint32_t lm_a_off =
        (uint32_t)((wm * 32 + (lane & 15)) * PITCH + (lane >> 4) * 16);
    const uint32_t lm_b_off =
        (uint32_t)((wn * 64 + (lane & 15)) * PITCH + (lane >> 4) * 16);

    int bufn = 0;
    int pbuf = 2;
    for (int c = 0; c < NCH; c++) {
        CP_WAIT1();
        __syncthreads();

        if (c + 2 < NCH) {
            const uint32_t base = sb + pbuf * BUFB;
            const int k0 = (c + 2) * 64;
#pragma unroll
            for (int j = 0; j < 4; j++) {
                int row = lrow + j * 32;
                uint32_t sa = base + row * PITCH + lch * 16;
                size_t ga = (size_t)(m0 + row) * HID_ + k0 + lch * 8;
                size_t gb = (size_t)(n0 + row) * HID_ + k0 + lch * 8;
                cpa16(sa, AH + ga);
                cpa16(sa + MATB, AL + ga);
                cpa16(sa + 2 * MATB, BH + gb);
            }
        }
        CP_COMMIT();

        const uint32_t cb = sb + bufn * BUFB;
#pragma unroll
        for (int ks = 0; ks < 4; ks++) {
            uint32_t ah[2][4], al[2][4];
#pragma unroll
            for (int mt = 0; mt < 2; mt++) {
                uint32_t addr = cb + lm_a_off + mt * (16 * PITCH) + ks * 32;
                LDSM4(ah[mt], addr);
                LDSM4(al[mt], addr + MATB);
            }
            uint32_t bh[8][2];
#pragma unroll
            for (int np = 0; np < 4; np++) {
                uint32_t addr = cb + 2 * MATB + lm_b_off + np * (16 * PITCH) + ks * 32;
                uint32_t r[4];
                LDSM4(r, addr);
                bh[2 * np][0] = r[0]; bh[2 * np + 1][0] = r[1];
                bh[2 * np][1] = r[2]; bh[2 * np + 1][1] = r[3];
            }
#pragma unroll
            for (int mt = 0; mt < 2; mt++)
#pragma unroll
                for (int nt = 0; nt < 8; nt++) {
                    MMAF32(acc[mt][nt], ah[mt], bh[nt]);
                    MMAF32(acc[mt][nt], al[mt], bh[nt]);
                }
        }
        bufn = (bufn == 2) ? 0 : bufn + 1;
        pbuf = (pbuf == 2) ? 0 : pbuf + 1;
    }

    // ------------------------------ Epilogue ------------------------------
    const int qrow = lane >> 2;
    const int qcol = (lane & 3) * 2;

    if (MODE == 1 && widx < 2) {
        // Q or K head tile: stage fp32 acc through SMEM, apply RoPE, emit fp16.
        float* st = (float*)dsm;                 // 128 rows x pitch 132 floats
        __syncthreads();                         // all warps done with pipeline bufs
#pragma unroll
        for (int mt = 0; mt < 2; mt++)
#pragma unroll
            for (int half_ = 0; half_ < 2; half_++) {
                const int row = wm * 32 + mt * 16 + qrow + half_ * 8;
#pragma unroll
                for (int nt = 0; nt < 8; nt++) {
                    int col = wn * 64 + nt * 8 + qcol;
                    st[row * 132 + col] = acc[mt][nt][half_ * 2];
                    st[row * 132 + col + 1] = acc[mt][nt][half_ * 2 + 1];
                }
            }
        __syncthreads();
#pragma unroll
        for (int i = 0; i < 32; i++) {
            int p = t + i * 256;                 // 0..8191
            int row = p >> 6;                    // 0..127
            int d = p & 63;                      // 0..63
            float x0 = st[row * 132 + d];
            float x1 = st[row * 132 + d + 64];
            const int m = m0 + row;
            const int s_ = m & (S_ - 1);
            const int b_ = m >> 11;
            float c0 = cosb[s_ * D_ + d], c1 = cosb[s_ * D_ + d + 64];
            float s0 = sinb[s_ * D_ + d], s1 = sinb[s_ * D_ + d + 64];
            float a = x0 * c0 - x1 * s0;         // x1*cos + (-x2)*sin
            float b = x1 * c1 + x0 * s1;         // x2*cos + ( x1)*sin
            size_t base = (((size_t)b_ * H_ + nblk) * S_ + s_) * D_;
            if (widx == 0) {
                unsigned short h, l;
                split1(a, h, l);
                g_qh[base + d] = __ushort_as_half(h);
                g_ql[base + d] = __ushort_as_half(l);
                split1(b, h, l);
                g_qh[base + d + 64] = __ushort_as_half(h);
                g_ql[base + d + 64] = __ushort_as_half(l);
            } else {
                g_kh[base + d] = __float2half_rn(a);
                g_kh[base + d + 64] = __float2half_rn(b);
            }
        }
    } else {
#pragma unroll
        for (int mt = 0; mt < 2; mt++) {
#pragma unroll
            for (int half_ = 0; half_ < 2; half_++) {
                const int m = m0 + wm * 32 + mt * 16 + qrow + half_ * 8;
                if (MODE == 1) {
                    // V: round to fp16 hi directly
                    int b_ = m >> 11, s_ = m & (S_ - 1);
                    size_t base = (((size_t)b_ * H_ + nblk) * S_ + s_) * D_;
#pragma unroll
                    for (int nt = 0; nt < 8; nt++) {
                        int col = wn * 64 + nt * 8 + qcol;
                        *(uint32_t*)(g_vh + base + col) =
                            f2h2(acc[mt][nt][half_ * 2], acc[mt][nt][half_ * 2 + 1]);
                    }
                } else {
                    size_t base = (size_t)m * HID_ + n0;
#pragma unroll
                    for (int nt = 0; nt < 8; nt++) {
                        int col = wn * 64 + nt * 8 + qcol;
                        *(float2*)(Cout + base + col) =
                            make_float2(acc[mt][nt][half_ * 2],
                                        acc[mt][nt][half_ * 2 + 1]);
                    }
                }
            }
        }
    }
}

// ---------------------------------------------------------------------------
// Flash attention, fp16x2 mma (Qh*Kh + Ql*Kh; Ph*Vh + Pl*Vh).
// SMEM: Qh, Ql, Kh, Vh each [128][128] fp16 at 272B pitch = 136KB.
// Epilogue writes g_xhi/g_xlo splits directly (feeds O-projection).
// ---------------------------------------------------------------------------
#define AP   272
#define AMAT (128 * AP)
#define ATTN_SMEM (4 * AMAT)          // 139264

__global__ __launch_bounds__(256, 1) void attn_mma_kernel() {
    extern __shared__ char sm8[];
    const uint32_t sb = smem_u32(sm8);
    const uint32_t Qh = sb,            Ql = sb + AMAT;
    const uint32_t Kh = sb + 2 * AMAT, Vh = sb + 3 * AMAT;

    const int t = threadIdx.x, lane = t & 31, wid = t >> 5;
    const int bh = blockIdx.y;
    const int q0 = blockIdx.x * 128;
    const size_t qoff = ((size_t)bh * S_ + q0) * D_;
    const size_t koff = (size_t)bh * S_ * D_;

#pragma unroll
    for (int j = 0; j < 8; j++) {
        int idx = t + j * 256;
        int row = idx >> 4, ch = idx & 15;
        uint32_t so = (uint32_t)(row * AP + ch * 16);
        size_t go = qoff + (size_t)row * D_ + ch * 8;
        cpa16(Qh + so, g_qh + go);
        cpa16(Ql + so, g_ql + go);
    }
    CP_COMMIT();

    float sa[16][4];
    float oa[16][4];
#pragma unroll
    for (int i = 0; i < 16; i++)
#pragma unroll
        for (int j = 0; j < 4; j++) oa[i][j] = 0.f;
    float m0r = -1e30f, m1r = -1e30f, l0r = 0.f, l1r = 0.f;

    const float scale = 0.088388347648318447f;
    const uint32_t a_off =
        (uint32_t)((wid * 16 + (lane & 15)) * AP + (lane >> 4) * 16);
    const uint32_t lm_lo = (uint32_t)((lane & 15) * AP + (lane >> 4) * 16);

    for (int kt = 0; kt < S_ / 128; kt++) {
        __syncthreads();
#pragma unroll
        for (int j = 0; j < 8; j++) {
            int idx = t + j * 256;
            int row = idx >> 4, ch = idx & 15;
            uint32_t so = (uint32_t)(row * AP + ch * 16);
            size_t go = koff + (size_t)(kt * 128 + row) * D_ + ch * 8;
            cpa16(Kh + so, g_kh + go);
        }
        CP_COMMIT();
#pragma unroll
        for (int j = 0; j < 8; j++) {
            int idx = t + j * 256;
            int row = idx >> 4, ch = idx & 15;
            uint32_t so = (uint32_t)(row * AP + ch * 16);
            size_t go = koff + (size_t)(kt * 128 + row) * D_ + ch * 8;
            cpa16(Vh + so, g_vh + go);
        }
        CP_COMMIT();

        CP_WAIT1();
        __syncthreads();

#pragma unroll
        for (int i = 0; i < 16; i++)
#pragma unroll
            for (int j = 0; j < 4; j++) sa[i][j] = 0.f;

#pragma unroll
        for (int ks = 0; ks < 8; ks++) {
            uint32_t qh[4], ql[4];
            LDSM4(qh, Qh + a_off + ks * 32);
            LDSM4(ql, Ql + a_off + ks * 32);
#pragma unroll
            for (int np = 0; np < 8; np++) {
                uint32_t boff = lm_lo + (uint32_t)(np * 16 * AP) + ks * 32;
                uint32_t r[4], kh0[2], kh1[2];
                LDSM4(r, Kh + boff);
                kh0[0] = r[0]; kh1[0] = r[1]; kh0[1] = r[2]; kh1[1] = r[3];
                MMAF32(sa[2 * np], qh, kh0);
                MMAF32(sa[2 * np], ql, kh0);
                MMAF32(sa[2 * np + 1], qh, kh1);
                MMAF32(sa[2 * np + 1], ql, kh1);
            }
        }

        // ---- online softmax ----
        float rm0 = -1e30f, rm1 = -1e30f;
#pragma unroll
        for (int nt = 0; nt < 16; nt++) {
            rm0 = fmaxf(rm0, fmaxf(sa[nt][0], sa[nt][1]));
            rm1 = fmaxf(rm1, fmaxf(sa[nt][2], sa[nt][3]));
        }
#pragma unroll
        for (int off = 1; off <= 2; off <<= 1) {
            rm0 = fmaxf(rm0, __shfl_xor_sync(0xffffffffu, rm0, off));
            rm1 = fmaxf(rm1, __shfl_xor_sync(0xffffffffu, rm1, off));
        }
        float mn0 = fmaxf(m0r, rm0 * scale);
        float mn1 = fmaxf(m1r, rm1 * scale);
        float al0 = __expf(m0r - mn0);
        float al1 = __expf(m1r - mn1);
        m0r = mn0;
        m1r = mn1;
        float rs0 = 0.f, rs1 = 0.f;
#pragma unroll
        for (int nt = 0; nt < 16; nt++) {
            float p0 = __expf(fmaf(sa[nt][0], scale, -mn0));
            float p1 = __expf(fmaf(sa[nt][1], scale, -mn0));
            float p2 = __expf(fmaf(sa[nt][2], scale, -mn1));
            float p3 = __expf(fmaf(sa[nt][3], scale, -mn1));
            sa[nt][0] = p0; sa[nt][1] = p1; sa[nt][2] = p2; sa[nt][3] = p3;
            rs0 += p0 + p1;
            rs1 += p2 + p3;
        }
#pragma unroll
        for (int off = 1; off <= 2; off <<= 1) {
            rs0 += __shfl_xor_sync(0xffffffffu, rs0, off);
            rs1 += __shfl_xor_sync(0xffffffffu, rs1, off);
        }
        l0r = l0r * al0 + rs0;
        l1r = l1r * al1 + rs1;
#pragma unroll
        for (int nt = 0; nt < 16; nt++) {
            oa[nt][0] *= al0;
            oa[nt][1] *= al0;
            oa[nt][2] *= al1;
            oa[nt][3] *= al1;
        }

        CP_WAIT0();
        __syncthreads();

        // ---- O += P V (Ph + Pl, both f32-accum) ----
#pragma unroll
        for (int ks = 0; ks < 8; ks++) {
            uint32_t aH[4], aL[4];
#pragma unroll
            for (int g = 0; g < 2; g++) {
                const int tt = 2 * ks + g;
                float x0 = sa[tt][0], y0 = sa[tt][1];
                float x1 = sa[tt][2], y1 = sa[tt][3];
                uint32_t h0 = f2h2(x0, y0);
                uint32_t h1 = f2h2(x1, y1);
                float2 b0 = h2f2(h0);
                float2 b1 = h2f2(h1);
                aH[2 * g]     = h0;
                aH[2 * g + 1] = h1;
                aL[2 * g]     = f2h2(x0 - b0.x, y0 - b0.y);
                aL[2 * g + 1] = f2h2(x1 - b1.x, y1 - b1.y);
            }
            const uint32_t vbase = lm_lo + (uint32_t)(ks * 16 * AP);
#pragma unroll
            for (int np = 0; np < 8; np++) {
                uint32_t r[4], vh0[2], vh1[2];
                LDSM4T(r, Vh + vbase + np * 32);
                vh0[0] = r[0]; vh0[1] = r[1]; vh1[0] = r[2]; vh1[1] = r[3];
                MMAF32(oa[2 * np], aH, vh0);
                MMAF32(oa[2 * np], aL, vh0);
                MMAF32(oa[2 * np + 1], aH, vh1);
                MMAF32(oa[2 * np + 1], aL, vh1);
            }
        }
    }

    // ---- finalize: write xhi/xlo fp16 splits of attn output directly ----
    const int b_ = bh >> 4, h = bh & 15;
    const int row0 = q0 + wid * 16 + (lane >> 2);
    const float inv0 = 1.0f / l0r, inv1 = 1.0f / l1r;
    const size_t base0 = ((size_t)b_ * S_ + row0) * HID_ + h * D_;
    const size_t base1 = ((size_t)b_ * S_ + row0 + 8) * HID_ + h * D_;
    const int col0 = (lane & 3) * 2;
#pragma unroll
    for (int nt = 0; nt < 16; nt++) {
        int col = 8 * nt + col0;
        float x0 = oa[nt][0] * inv0, y0 = oa[nt][1] * inv0;
        float x1 = oa[nt][2] * inv1, y1 = oa[nt][3] * inv1;
        unsigned short hx, lx, hy, ly;
        split1(x0, hx, lx);
        split1(y0, hy, ly);
        *(uint32_t*)(g_xhi + base0 + col) = (uint32_t)hx | ((uint32_t)hy << 16);
        *(uint32_t*)(g_xlo + base0 + col) = (uint32_t)lx | ((uint32_t)ly << 16);
        split1(x1, hx, lx);
        split1(y1, hy, ly);
        *(uint32_t*)(g_xhi + base1 + col) = (uint32_t)hx | ((uint32_t)hy << 16);
        *(uint32_t*)(g_xlo + base1 + col) = (uint32_t)lx | ((uint32_t)ly << 16);
    }
}

// ---------------------------------------------------------------------------
// Launch
// ---------------------------------------------------------------------------
extern "C" void kernel_launch(void* const* d_in, const int* in_sizes, int n_in,
                              void* d_out, int out_size) {
    const float* X = (const float*)d_in[0];
    const float* cosb = (const float*)d_in[1];
    const float* sinb = (const float*)d_in[2];
    const float* Wq = (const float*)d_in[3];
    const float* Wk = (const float*)d_in[4];
    const float* Wv = (const float*)d_in[5];
    const float* Wo = (const float*)d_in[6];
    float* out = (float*)d_out;

    cudaFuncSetAttribute(mma_gemm<0>, cudaFuncAttributeMaxDynamicSharedMemorySize, GEMM_SMEM);
    cudaFuncSetAttribute(mma_gemm<1>, cudaFuncAttributeMaxDynamicSharedMemorySize, GEMM_SMEM);
    cudaFuncSetAttribute(attn_mma_kernel, cudaFuncAttributeMaxDynamicSharedMemorySize, ATTN_SMEM);

    // all weight conversions in one launch; activations split
    wsplit_kernel<<<dim3(64, 64, 4), dim3(32, 8)>>>(Wq, Wk, Wv, Wo);
    asplit_kernel<<<(M_ * HID_ / 4) / 256, 256>>>(X);

    // fused QKV projection with RoPE + fp16 split in epilogue
    mma_gemm<1><<<dim3(48, M_ / 128), 256, GEMM_SMEM>>>(nullptr, cosb, sinb);

    // attention writes g_xhi/g_xlo directly
    attn_mma_kernel<<<dim3(S_ / 128, B_ * H_), 256, ATTN_SMEM>>>();

    // O projection
    mma_gemm<0><<<dim3(HID_ / 128, M_ / 128), 256, GEMM_SMEM>>>(out, nullptr, nullptr);
}

// round 10
// speedup vs baseline: 1.5543x; 1.0146x over previous
#include <cuda_runtime.h>
#include <cuda_fp16.h>
#include <cstdint>

// ---------------------------------------------------------------------------
// Problem constants
// ---------------------------------------------------------------------------
#define B_ 2
#define S_ 2048
#define H_ 16
#define D_ 128
#define HID_ 2048
#define M_ (B_ * S_)   // 4096

// Scratch (device globals — allocation-free per harness rules)
__device__ float g_q[(size_t)B_ * H_ * S_ * D_];   // fp32 Q pre-rope [b,h,s,d]
__device__ float g_k[(size_t)B_ * H_ * S_ * D_];   // fp32 K pre-rope

// fp16 buffers. Activations split hi/lo; weights hi only (2-term emulation).
__device__ __half g_xhi[(size_t)M_ * HID_];
__device__ __half g_xlo[(size_t)M_ * HID_];
__device__ __half g_bhi[(size_t)4 * HID_ * HID_];

// fp16 attention operands [b,h,s,d]: Q split hi/lo; K, V hi only.
#define QKV_ELEMS ((size_t)B_ * H_ * S_ * D_)
__device__ __half g_qh[QKV_ELEMS];
__device__ __half g_ql[QKV_ELEMS];
__device__ __half g_kh[QKV_ELEMS];
__device__ __half g_vh[QKV_ELEMS];

// ---------------------------------------------------------------------------
// PTX helpers (non-'a' features only)
// ---------------------------------------------------------------------------
__device__ __forceinline__ uint32_t smem_u32(const void* p) {
    uint32_t a;
    asm("{ .reg .u64 t; cvta.to.shared.u64 t, %1; cvt.u32.u64 %0, t; }"
        : "=r"(a) : "l"(p));
    return a;
}
__device__ __forceinline__ void cpa16(uint32_t s, const void* g) {
    asm volatile("cp.async.cg.shared.global [%0], [%1], 16;" :: "r"(s), "l"(g));
}
#define CP_COMMIT() asm volatile("cp.async.commit_group;" ::: "memory")
#define CP_WAIT0()  asm volatile("cp.async.wait_group 0;" ::: "memory")
#define CP_WAIT1()  asm volatile("cp.async.wait_group 1;" ::: "memory")

#define LDSM4(r, addr)                                                        \
    asm volatile("ldmatrix.sync.aligned.m8n8.x4.shared.b16 {%0,%1,%2,%3}, [%4];" \
                 : "=r"((r)[0]), "=r"((r)[1]), "=r"((r)[2]), "=r"((r)[3])     \
                 : "r"(addr))
#define LDSM4T(r, addr)                                                       \
    asm volatile("ldmatrix.sync.aligned.m8n8.x4.trans.shared.b16 {%0,%1,%2,%3}, [%4];" \
                 : "=r"((r)[0]), "=r"((r)[1]), "=r"((r)[2]), "=r"((r)[3])     \
                 : "r"(addr))

#define MMAF32(d, a, b)                                                       \
    asm volatile(                                                             \
        "mma.sync.aligned.m16n8k16.row.col.f32.f16.f16.f32 "                  \
        "{%0,%1,%2,%3}, {%4,%5,%6,%7}, {%8,%9}, {%0,%1,%2,%3};"               \
        : "+f"((d)[0]), "+f"((d)[1]), "+f"((d)[2]), "+f"((d)[3])              \
        : "r"((a)[0]), "r"((a)[1]), "r"((a)[2]), "r"((a)[3]),                 \
          "r"((b)[0]), "r"((b)[1]))

__device__ __forceinline__ float2 h2f2(uint32_t u) {
    __half2 h = *(__half2*)&u;
    return __half22float2(h);
}
__device__ __forceinline__ uint32_t f2h2(float x, float y) {
    __half2 h = __float22half2_rn(make_float2(x, y));
    return *(uint32_t*)&h;
}

// fp32 -> fp16 hi/lo split
__device__ __forceinline__ void split1(float x, unsigned short& h, unsigned short& l) {
    __half hb = __float2half_rn(x);
    __half lb = __float2half_rn(x - __half2float(hb));
    h = __half_as_ushort(hb);
    l = __half_as_ushort(lb);
}

// ---------------------------------------------------------------------------
// Activations: X [M,K] fp32 -> g_xhi/g_xlo fp16.
// ---------------------------------------------------------------------------
__global__ void asplit_kernel(const float* __restrict__ src) {
    size_t i = (size_t)blockIdx.x * 256 + threadIdx.x;
    float4 v = ((const float4*)src)[i];
    ushort4 h, l;
    split1(v.x, h.x, l.x);
    split1(v.y, h.y, l.y);
    split1(v.z, h.z, l.z);
    split1(v.w, h.w, l.w);
    ((ushort4*)g_xhi)[i] = h;
    ((ushort4*)g_xlo)[i] = l;
}

// All 4 weights in one launch: W [K,N] fp32 -> g_bhi slot z, [N,K] fp16 hi.
__global__ void wsplit_kernel(const float* __restrict__ W0,
                              const float* __restrict__ W1,
                              const float* __restrict__ W2,
                              const float* __restrict__ W3) {
    __shared__ float ts[32][33];
    const int tx = threadIdx.x, ty = threadIdx.y;
    const int n0 = blockIdx.x * 32, k0 = blockIdx.y * 32;
    const int widx = blockIdx.z;
    const float* W = (widx == 0) ? W0 : (widx == 1) ? W1 : (widx == 2) ? W2 : W3;
    __half* bh = g_bhi + (size_t)widx * HID_ * HID_;
#pragma unroll
    for (int i = 0; i < 4; i++)
        ts[ty + 8 * i][tx] = W[(size_t)(k0 + ty + 8 * i) * HID_ + n0 + tx];
    __syncthreads();
#pragma unroll
    for (int i = 0; i < 4; i++) {
        int n = n0 + ty + 8 * i;
        int k = k0 + tx;
        bh[(size_t)n * HID_ + k] = __float2half_rn(ts[tx][ty + 8 * i]);
    }
}

// ---------------------------------------------------------------------------
// mma.sync fp16x2 GEMM (Ah*Bh + Al*Bh, both f32-accum), 3-stage pipeline.
// hi/lo mma streams separated: RAW distance 16 (latency hiding at 2 w/SMSP).
// MODE==1: fused QKV (blockIdx.x = widx*16 + head). MODE==0: O projection.
// ---------------------------------------------------------------------------
#define PITCH 144
#define MATB  (128 * PITCH)          // 18432
#define BUFB  (3 * MATB)             // 55296 (Ah, Al, Bh)
#define GEMM_SMEM (3 * BUFB)         // 165888
#define NCH (HID_ / 64)              // 32

template <int MODE>
__global__ __launch_bounds__(256, 1) void mma_gemm(float* __restrict__ Cout) {
    extern __shared__ char dsm[];
    const uint32_t sb = smem_u32(dsm);
    const int t = threadIdx.x;
    const int lane = t & 31, wid = t >> 5;
    const int wm = wid & 3, wn = wid >> 2;
    const int m0 = blockIdx.y * 128;
    const int widx = (MODE == 1) ? (blockIdx.x >> 4) : 3;
    const int nblk = (MODE == 1) ? (blockIdx.x & 15) : blockIdx.x;
    const int n0 = nblk * 128;

    const __half* __restrict__ AH = g_xhi;
    const __half* __restrict__ AL = g_xlo;
    const __half* __restrict__ BH = g_bhi + (size_t)widx * HID_ * HID_;

    float acc[2][8][4];
#pragma unroll
    for (int i = 0; i < 2; i++)
#pragma unroll
        for (int j = 0; j < 8; j++)
#pragma unroll
            for (int k = 0; k < 4; k++) acc[i][j][k] = 0.f;

    const int lrow = t >> 3;
    const int lch = t & 7;

#pragma unroll
    for (int s = 0; s < 2; s++) {
        const uint32_t base = sb + s * BUFB;
        const int k0 = s * 64;
#pragma unroll
        for (int j = 0; j < 4; j++) {
            int row = lrow + j * 32;
            uint32_t sa = base + row * PITCH + lch * 16;
            size_t ga = (size_t)(m0 + row) * HID_ + k0 + lch * 8;
            size_t gb = (size_t)(n0 + row) * HID_ + k0 + lch * 8;
            cpa16(sa, AH + ga);
            cpa16(sa + MATB, AL + ga);
            cpa16(sa + 2 * MATB, BH + gb);
        }
        CP_COMMIT();
    }

    const uint32_t lm_a_off =
        (uint32_t)((wm * 32 + (lane & 15)) * PITCH + (lane >> 4) * 16);
    const uint32_t lm_b_off =
        (uint32_t)((wn * 64 + (lane & 15)) * PITCH + (lane >> 4) * 16);

    int bufn = 0;
    int pbuf = 2;
    for (int c = 0; c < NCH; c++) {
        CP_WAIT1();
        __syncthreads();

        if (c + 2 < NCH) {
            const uint32_t base = sb + pbuf * BUFB;
            const int k0 = (c + 2) * 64;
#pragma unroll
            for (int j = 0; j < 4; j++) {
                int row = lrow + j * 32;
                uint32_t sa = base + row * PITCH + lch * 16;
                size_t ga = (size_t)(m0 + row) * HID_ + k0 + lch * 8;
                size_t gb = (size_t)(n0 + row) * HID_ + k0 + lch * 8;
                cpa16(sa, AH + ga);
                cpa16(sa + MATB, AL + ga);
                cpa16(sa + 2 * MATB, BH + gb);
            }
        }
        CP_COMMIT();

        const uint32_t cb = sb + bufn * BUFB;
#pragma unroll
        for (int ks = 0; ks < 4; ks++) {
            uint32_t ah[2][4], al[2][4];
#pragma unroll
            for (int mt = 0; mt < 2; mt++) {
                uint32_t addr = cb + lm_a_off + mt * (16 * PITCH) + ks * 32;
                LDSM4(ah[mt], addr);
                LDSM4(al[mt], addr + MATB);
            }
            uint32_t bh[8][2];
#pragma unroll
            for (int np = 0; np < 4; np++) {
                uint32_t addr = cb + 2 * MATB + lm_b_off + np * (16 * PITCH) + ks * 32;
                uint32_t r[4];
                LDSM4(r, addr);
                bh[2 * np][0] = r[0]; bh[2 * np + 1][0] = r[1];
                bh[2 * np][1] = r[2]; bh[2 * np + 1][1] = r[3];
            }
            // hi stream: 16 independent mma
#pragma unroll
            for (int mt = 0; mt < 2; mt++)
#pragma unroll
                for (int nt = 0; nt < 8; nt++)
                    MMAF32(acc[mt][nt], ah[mt], bh[nt]);
            // lo stream: RAW distance 16 from matching hi
#pragma unroll
            for (int mt = 0; mt < 2; mt++)
#pragma unroll
                for (int nt = 0; nt < 8; nt++)
                    MMAF32(acc[mt][nt], al[mt], bh[nt]);
        }
        bufn = (bufn == 2) ? 0 : bufn + 1;
        pbuf = (pbuf == 2) ? 0 : pbuf + 1;
    }

    // Epilogue
    const int qrow = lane >> 2;
    const int qcol = (lane & 3) * 2;
#pragma unroll
    for (int mt = 0; mt < 2; mt++) {
#pragma unroll
        for (int half_ = 0; half_ < 2; half_++) {
            const int m = m0 + wm * 32 + mt * 16 + qrow + half_ * 8;
            if (MODE == 1 && widx == 2) {
                int b_ = m >> 11, s_ = m & (S_ - 1);
                size_t base = (((size_t)b_ * H_ + nblk) * S_ + s_) * D_;
#pragma unroll
                for (int nt = 0; nt < 8; nt++) {
                    int col = wn * 64 + nt * 8 + qcol;
                    *(uint32_t*)(g_vh + base + col) =
                        f2h2(acc[mt][nt][half_ * 2], acc[mt][nt][half_ * 2 + 1]);
                }
            } else {
                float* dst;
                size_t base;
                if (MODE == 0) {
                    dst = Cout;
                    base = (size_t)m * HID_ + n0;
                } else {
                    int b_ = m >> 11, s_ = m & (S_ - 1);
                    dst = (widx == 0) ? g_q : g_k;
                    base = (((size_t)b_ * H_ + nblk) * S_ + s_) * D_;
                }
#pragma unroll
                for (int nt = 0; nt < 8; nt++) {
                    int col = wn * 64 + nt * 8 + qcol;
                    *(float2*)(dst + base + col) =
                        make_float2(acc[mt][nt][half_ * 2], acc[mt][nt][half_ * 2 + 1]);
                }
            }
        }
    }
}

// ---------------------------------------------------------------------------
// RoPE: read fp32 g_q/g_k, rotate, emit qh/ql (fp16 split) and kh (round).
// ---------------------------------------------------------------------------
__global__ void rope_split_kernel(const float* __restrict__ cosb,
                                  const float* __restrict__ sinb) {
    int tid = blockIdx.x * 256 + threadIdx.x;
    int d = tid & 63;
    int s = (tid >> 6) & (S_ - 1);
    int bh = tid >> 17;
    size_t base = ((size_t)bh * S_ + s) * D_;
    float c0 = cosb[s * D_ + d], c1 = cosb[s * D_ + d + 64];
    float s0 = sinb[s * D_ + d], s1 = sinb[s * D_ + d + 64];

    float q0 = g_q[base + d], q1 = g_q[base + d + 64];
    float k0 = g_k[base + d], k1 = g_k[base + d + 64];
    float qa = q0 * c0 - q1 * s0;
    float qb = q1 * c1 + q0 * s1;
    float ka = k0 * c0 - k1 * s0;
    float kb = k1 * c1 + k0 * s1;

    unsigned short h, l;
    split1(qa, h, l);
    g_qh[base + d] = __ushort_as_half(h);
    g_ql[base + d] = __ushort_as_half(l);
    split1(qb, h, l);
    g_qh[base + d + 64] = __ushort_as_half(h);
    g_ql[base + d + 64] = __ushort_as_half(l);
    g_kh[base + d] = __float2half_rn(ka);
    g_kh[base + d + 64] = __float2half_rn(kb);
}

// ---------------------------------------------------------------------------
// Flash attention, fp16x2 mma; hi/lo streams separated (RAW distance 8).
// SMEM: Qh, Ql, Kh, Vh each [128][128] fp16 at 272B pitch = 136KB.
// Epilogue writes g_xhi/g_xlo splits directly (feeds O-projection).
// ---------------------------------------------------------------------------
#define AP   272
#define AMAT (128 * AP)
#define ATTN_SMEM (4 * AMAT)          // 139264

__global__ __launch_bounds__(256, 1) void attn_mma_kernel() {
    extern __shared__ char sm8[];
    const uint32_t sb = smem_u32(sm8);
    const uint32_t Qh = sb,            Ql = sb + AMAT;
    const uint32_t Kh = sb + 2 * AMAT, Vh = sb + 3 * AMAT;

    const int t = threadIdx.x, lane = t & 31, wid = t >> 5;
    const int bh = blockIdx.y;
    const int q0 = blockIdx.x * 128;
    const size_t qoff = ((size_t)bh * S_ + q0) * D_;
    const size_t koff = (size_t)bh * S_ * D_;

#pragma unroll
    for (int j = 0; j < 8; j++) {
        int idx = t + j * 256;
        int row = idx >> 4, ch = idx & 15;
        uint32_t so = (uint32_t)(row * AP + ch * 16);
        size_t go = qoff + (size_t)row * D_ + ch * 8;
        cpa16(Qh + so, g_qh + go);
        cpa16(Ql + so, g_ql + go);
    }
    CP_COMMIT();

    float sa[16][4];
    float oa[16][4];
#pragma unroll
    for (int i = 0; i < 16; i++)
#pragma unroll
        for (int j = 0; j < 4; j++) oa[i][j] = 0.f;
    float m0r = -1e30f, m1r = -1e30f, l0r = 0.f, l1r = 0.f;

    const float scale = 0.088388347648318447f;
    const uint32_t a_off =
        (uint32_t)((wid * 16 + (lane & 15)) * AP + (lane >> 4) * 16);
    const uint32_t lm_lo = (uint32_t)((lane & 15) * AP + (lane >> 4) * 16);

    for (int kt = 0; kt < S_ / 128; kt++) {
        __syncthreads();
#pragma unroll
        for (int j = 0; j < 8; j++) {
            int idx = t + j * 256;
            int row = idx >> 4, ch = idx & 15;
            uint32_t so = (uint32_t)(row * AP + ch * 16);
            size_t go = koff + (size_t)(kt * 128 + row) * D_ + ch * 8;
            cpa16(Kh + so, g_kh + go);
        }
        CP_COMMIT();
#pragma unroll
        for (int j = 0; j < 8; j++) {
            int idx = t + j * 256;
            int row = idx >> 4, ch = idx & 15;
            uint32_t so = (uint32_t)(row * AP + ch * 16);
            size_t go = koff + (size_t)(kt * 128 + row) * D_ + ch * 8;
            cpa16(Vh + so, g_vh + go);
        }
        CP_COMMIT();

        CP_WAIT1();
        __syncthreads();

#pragma unroll
        for (int i = 0; i < 16; i++)
#pragma unroll
            for (int j = 0; j < 4; j++) sa[i][j] = 0.f;

        // ---- S = Q K^T, hi/lo streams separated per np-half ----
#pragma unroll
        for (int ks = 0; ks < 8; ks++) {
            uint32_t qh[4], ql[4];
            LDSM4(qh, Qh + a_off + ks * 32);
            LDSM4(ql, Ql + a_off + ks * 32);
#pragma unroll
            for (int h2 = 0; h2 < 2; h2++) {
                uint32_t kA[4][2], kB[4][2];
#pragma unroll
                for (int j = 0; j < 4; j++) {
                    const int np = h2 * 4 + j;
                    uint32_t r[4];
                    LDSM4(r, Kh + lm_lo + (uint32_t)(np * 16 * AP) + ks * 32);
                    kA[j][0] = r[0]; kB[j][0] = r[1];
                    kA[j][1] = r[2]; kB[j][1] = r[3];
                }
#pragma unroll
                for (int j = 0; j < 4; j++) {
                    const int np = h2 * 4 + j;
                    MMAF32(sa[2 * np], qh, kA[j]);
                    MMAF32(sa[2 * np + 1], qh, kB[j]);
                }
#pragma unroll
                for (int j = 0; j < 4; j++) {
                    const int np = h2 * 4 + j;
                    MMAF32(sa[2 * np], ql, kA[j]);
                    MMAF32(sa[2 * np + 1], ql, kB[j]);
                }
            }
        }

        // ---- online softmax ----
        float rm0 = -1e30f, rm1 = -1e30f;
#pragma unroll
        for (int nt = 0; nt < 16; nt++) {
            rm0 = fmaxf(rm0, fmaxf(sa[nt][0], sa[nt][1]));
            rm1 = fmaxf(rm1, fmaxf(sa[nt][2], sa[nt][3]));
        }
#pragma unroll
        for (int off = 1; off <= 2; off <<= 1) {
            rm0 = fmaxf(rm0, __shfl_xor_sync(0xffffffffu, rm0, off));
            rm1 = fmaxf(rm1, __shfl_xor_sync(0xffffffffu, rm1, off));
        }
        float mn0 = fmaxf(m0r, rm0 * scale);
        float mn1 = fmaxf(m1r, rm1 * scale);
        float al0 = __expf(m0r - mn0);
        float al1 = __expf(m1r - mn1);
        m0r = mn0;
        m1r = mn1;
        float rs0 = 0.f, rs1 = 0.f;
#pragma unroll
        for (int nt = 0; nt < 16; nt++) {
            float p0 = __expf(fmaf(sa[nt][0], scale, -mn0));
            float p1 = __expf(fmaf(sa[nt][1], scale, -mn0));
            float p2 = __expf(fmaf(sa[nt][2], scale, -mn1));
            float p3 = __expf(fmaf(sa[nt][3], scale, -mn1));
            sa[nt][0] = p0; sa[nt][1] = p1; sa[nt][2] = p2; sa[nt][3] = p3;
            rs0 += p0 + p1;
            rs1 += p2 + p3;
        }
#pragma unroll
        for (int off = 1; off <= 2; off <<= 1) {
            rs0 += __shfl_xor_sync(0xffffffffu, rs0, off);
            rs1 += __shfl_xor_sync(0xffffffffu, rs1, off);
        }
        l0r = l0r * al0 + rs0;
        l1r = l1r * al1 + rs1;
#pragma unroll
        for (int nt = 0; nt < 16; nt++) {
            oa[nt][0] *= al0;
            oa[nt][1] *= al0;
            oa[nt][2] *= al1;
            oa[nt][3] *= al1;
        }

        CP_WAIT0();
        __syncthreads();

        // ---- O += P V, hi/lo streams separated per np-half ----
#pragma unroll
        for (int ks = 0; ks < 8; ks++) {
            uint32_t aH[4], aL[4];
#pragma unroll
            for (int g = 0; g < 2; g++) {
                const int tt = 2 * ks + g;
                float x0 = sa[tt][0], y0 = sa[tt][1];
                float x1 = sa[tt][2], y1 = sa[tt][3];
                uint32_t h0 = f2h2(x0, y0);
                uint32_t h1 = f2h2(x1, y1);
                float2 b0 = h2f2(h0);
                float2 b1 = h2f2(h1);
                aH[2 * g]     = h0;
                aH[2 * g + 1] = h1;
                aL[2 * g]     = f2h2(x0 - b0.x, y0 - b0.y);
                aL[2 * g + 1] = f2h2(x1 - b1.x, y1 - b1.y);
            }
            const uint32_t vbase = lm_lo + (uint32_t)(ks * 16 * AP);
#pragma unroll
            for (int h2 = 0; h2 < 2; h2++) {
                uint32_t vA[4][2], vB[4][2];
#pragma unroll
                for (int j = 0; j < 4; j++) {
                    const int np = h2 * 4 + j;
                    uint32_t r[4];
                    LDSM4T(r, Vh + vbase + np * 32);
                    vA[j][0] = r[0]; vA[j][1] = r[1];
                    vB[j][0] = r[2]; vB[j][1] = r[3];
                }
#pragma unroll
                for (int j = 0; j < 4; j++) {
                    const int np = h2 * 4 + j;
                    MMAF32(oa[2 * np], aH, vA[j]);
                    MMAF32(oa[2 * np + 1], aH, vB[j]);
                }
#pragma unroll
                for (int j = 0; j < 4; j++) {
                    const int np = h2 * 4 + j;
                    MMAF32(oa[2 * np], aL, vA[j]);
                    MMAF32(oa[2 * np + 1], aL, vB[j]);
                }
            }
        }
    }

    // ---- finalize: write xhi/xlo fp16 splits of attn output directly ----
    const int b_ = bh >> 4, h = bh & 15;
    const int row0 = q0 + wid * 16 + (lane >> 2);
    const float inv0 = 1.0f / l0r, inv1 = 1.0f / l1r;
    const size_t base0 = ((size_t)b_ * S_ + row0) * HID_ + h * D_;
    const size_t base1 = ((size_t)b_ * S_ + row0 + 8) * HID_ + h * D_;
    const int col0 = (lane & 3) * 2;
#pragma unroll
    for (int nt = 0; nt < 16; nt++) {
        int col = 8 * nt + col0;
        float x0 = oa[nt][0] * inv0, y0 = oa[nt][1] * inv0;
        float x1 = oa[nt][2] * inv1, y1 = oa[nt][3] * inv1;
        unsigned short hx, lx, hy, ly;
        split1(x0, hx, lx);
        split1(y0, hy, ly);
        *(uint32_t*)(g_xhi + base0 + col) = (uint32_t)hx | ((uint32_t)hy << 16);
        *(uint32_t*)(g_xlo + base0 + col) = (uint32_t)lx | ((uint32_t)ly << 16);
        split1(x1, hx, lx);
        split1(y1, hy, ly);
        *(uint32_t*)(g_xhi + base1 + col) = (uint32_t)hx | ((uint32_t)hy << 16);
        *(uint32_t*)(g_xlo + base1 + col) = (uint32_t)lx | ((uint32_t)ly << 16);
    }
}

// ---------------------------------------------------------------------------
// Launch
// ---------------------------------------------------------------------------
extern "C" void kernel_launch(void* const* d_in, const int* in_sizes, int n_in,
                              void* d_out, int out_size) {
    const float* X = (const float*)d_in[0];
    const float* cosb = (const float*)d_in[1];
    const float* sinb = (const float*)d_in[2];
    const float* Wq = (const float*)d_in[3];
    const float* Wk = (const float*)d_in[4];
    const float* Wv = (const float*)d_in[5];
    const float* Wo = (const float*)d_in[6];
    float* out = (float*)d_out;

    cudaFuncSetAttribute(mma_gemm<0>, cudaFuncAttributeMaxDynamicSharedMemorySize, GEMM_SMEM);
    cudaFuncSetAttribute(mma_gemm<1>, cudaFuncAttributeMaxDynamicSharedMemorySize, GEMM_SMEM);
    cudaFuncSetAttribute(attn_mma_kernel, cudaFuncAttributeMaxDynamicSharedMemorySize, ATTN_SMEM);

    // all weight conversions in one launch; activations split
    wsplit_kernel<<<dim3(64, 64, 4), dim3(32, 8)>>>(Wq, Wk, Wv, Wo);
    asplit_kernel<<<(M_ * HID_ / 4) / 256, 256>>>(X);

    // fused QKV projection
    mma_gemm<1><<<dim3(48, M_ / 128), 256, GEMM_SMEM>>>(nullptr);

    rope_split_kernel<<<(B_ * H_ * S_ * 64) / 256, 256>>>(cosb, sinb);

    // attention writes g_xhi/g_xlo directly
    attn_mma_kernel<<<dim3(S_ / 128, B_ * H_), 256, ATTN_SMEM>>>();

    // O projection
    mma_gemm<0><<<dim3(HID_ / 128, M_ / 128), 256, GEMM_SMEM>>>(out);
}

// round 11
// speedup vs baseline: 1.6910x; 1.0880x over previous
#include <cuda_runtime.h>
#include <cuda_fp16.h>
#include <cstdint>

// ---------------------------------------------------------------------------
// Problem constants
// ---------------------------------------------------------------------------
#define B_ 2
#define S_ 2048
#define H_ 16
#define D_ 128
#define HID_ 2048
#define M_ (B_ * S_)   // 4096

// Scratch (device globals — allocation-free per harness rules)
__device__ float g_q[(size_t)B_ * H_ * S_ * D_];   // fp32 Q pre-rope [b,h,s,d]
__device__ float g_k[(size_t)B_ * H_ * S_ * D_];   // fp32 K pre-rope

// fp16 buffers. Activations split hi/lo; weights hi only (2-term emulation).
__device__ __half g_xhi[(size_t)M_ * HID_];
__device__ __half g_xlo[(size_t)M_ * HID_];
__device__ __half g_bhi[(size_t)4 * HID_ * HID_];

// fp16 attention operands [b,h,s,d]: Q split hi/lo; K, V hi only.
#define QKV_ELEMS ((size_t)B_ * H_ * S_ * D_)
__device__ __half g_qh[QKV_ELEMS];
__device__ __half g_ql[QKV_ELEMS];
__device__ __half g_kh[QKV_ELEMS];
__device__ __half g_vh[QKV_ELEMS];

// ---------------------------------------------------------------------------
// PTX helpers (non-'a' features only)
// ---------------------------------------------------------------------------
__device__ __forceinline__ uint32_t smem_u32(const void* p) {
    uint32_t a;
    asm("{ .reg .u64 t; cvta.to.shared.u64 t, %1; cvt.u32.u64 %0, t; }"
        : "=r"(a) : "l"(p));
    return a;
}
__device__ __forceinline__ void cpa16(uint32_t s, const void* g) {
    asm volatile("cp.async.cg.shared.global [%0], [%1], 16;" :: "r"(s), "l"(g));
}
#define CP_COMMIT() asm volatile("cp.async.commit_group;" ::: "memory")
#define CP_WAIT0()  asm volatile("cp.async.wait_group 0;" ::: "memory")
#define CP_WAIT1()  asm volatile("cp.async.wait_group 1;" ::: "memory")

#define LDSM4(r, addr)                                                        \
    asm volatile("ldmatrix.sync.aligned.m8n8.x4.shared.b16 {%0,%1,%2,%3}, [%4];" \
                 : "=r"((r)[0]), "=r"((r)[1]), "=r"((r)[2]), "=r"((r)[3])     \
                 : "r"(addr))
#define LDSM4T(r, addr)                                                       \
    asm volatile("ldmatrix.sync.aligned.m8n8.x4.trans.shared.b16 {%0,%1,%2,%3}, [%4];" \
                 : "=r"((r)[0]), "=r"((r)[1]), "=r"((r)[2]), "=r"((r)[3])     \
                 : "r"(addr))

#define MMAF32(d, a, b)                                                       \
    asm volatile(                                                             \
        "mma.sync.aligned.m16n8k16.row.col.f32.f16.f16.f32 "                  \
        "{%0,%1,%2,%3}, {%4,%5,%6,%7}, {%8,%9}, {%0,%1,%2,%3};"               \
        : "+f"((d)[0]), "+f"((d)[1]), "+f"((d)[2]), "+f"((d)[3])              \
        : "r"((a)[0]), "r"((a)[1]), "r"((a)[2]), "r"((a)[3]),                 \
          "r"((b)[0]), "r"((b)[1]))

__device__ __forceinline__ float2 h2f2(uint32_t u) {
    __half2 h = *(__half2*)&u;
    return __half22float2(h);
}
__device__ __forceinline__ uint32_t f2h2(float x, float y) {
    __half2 h = __float22half2_rn(make_float2(x, y));
    return *(uint32_t*)&h;
}

// fp32 -> fp16 hi/lo split
__device__ __forceinline__ void split1(float x, unsigned short& h, unsigned short& l) {
    __half hb = __float2half_rn(x);
    __half lb = __float2half_rn(x - __half2float(hb));
    h = __half_as_ushort(hb);
    l = __half_as_ushort(lb);
}

// ---------------------------------------------------------------------------
// Activations: X [M,K] fp32 -> g_xhi/g_xlo fp16.
// ---------------------------------------------------------------------------
__global__ void asplit_kernel(const float* __restrict__ src) {
    size_t i = (size_t)blockIdx.x * 256 + threadIdx.x;
    float4 v = ((const float4*)src)[i];
    ushort4 h, l;
    split1(v.x, h.x, l.x);
    split1(v.y, h.y, l.y);
    split1(v.z, h.z, l.z);
    split1(v.w, h.w, l.w);
    ((ushort4*)g_xhi)[i] = h;
    ((ushort4*)g_xlo)[i] = l;
}

// All 4 weights in one launch: W [K,N] fp32 -> g_bhi slot z, [N,K] fp16 hi.
__global__ void wsplit_kernel(const float* __restrict__ W0,
                              const float* __restrict__ W1,
                              const float* __restrict__ W2,
                              const float* __restrict__ W3) {
    __shared__ float ts[32][33];
    const int tx = threadIdx.x, ty = threadIdx.y;
    const int n0 = blockIdx.x * 32, k0 = blockIdx.y * 32;
    const int widx = blockIdx.z;
    const float* W = (widx == 0) ? W0 : (widx == 1) ? W1 : (widx == 2) ? W2 : W3;
    __half* bh = g_bhi + (size_t)widx * HID_ * HID_;
#pragma unroll
    for (int i = 0; i < 4; i++)
        ts[ty + 8 * i][tx] = W[(size_t)(k0 + ty + 8 * i) * HID_ + n0 + tx];
    __syncthreads();
#pragma unroll
    for (int i = 0; i < 4; i++) {
        int n = n0 + ty + 8 * i;
        int k = k0 + tx;
        bh[(size_t)n * HID_ + k] = __float2half_rn(ts[tx][ty + 8 * i]);
    }
}

// ---------------------------------------------------------------------------
// mma.sync fp16x2 GEMM (Ah*Bh + Al*Bh, both f32-accum).
// 2-stage double buffer, 2 CTAs/SM (4 warps/SMSP: co-resident CTA covers
// this CTA's load/sync/epilogue bubbles on the tensor pipe).
// MODE==1: fused QKV (blockIdx.x = widx*16 + head). MODE==0: O projection.
// ---------------------------------------------------------------------------
#define PITCH 144
#define MATB  (128 * PITCH)          // 18432
#define BUFB  (3 * MATB)             // 55296 (Ah, Al, Bh)
#define GEMM_SMEM (2 * BUFB)         // 110592 -> two CTAs fit per SM
#define NCH (HID_ / 64)              // 32

template <int MODE>
__global__ __launch_bounds__(256, 2) void mma_gemm(float* __restrict__ Cout) {
    extern __shared__ char dsm[];
    const uint32_t sb = smem_u32(dsm);
    const int t = threadIdx.x;
    const int lane = t & 31, wid = t >> 5;
    const int wm = wid & 3, wn = wid >> 2;
    const int m0 = blockIdx.y * 128;
    const int widx = (MODE == 1) ? (blockIdx.x >> 4) : 3;
    const int nblk = (MODE == 1) ? (blockIdx.x & 15) : blockIdx.x;
    const int n0 = nblk * 128;

    const __half* __restrict__ AH = g_xhi;
    const __half* __restrict__ AL = g_xlo;
    const __half* __restrict__ BH = g_bhi + (size_t)widx * HID_ * HID_;

    float acc[2][8][4];
#pragma unroll
    for (int i = 0; i < 2; i++)
#pragma unroll
        for (int j = 0; j < 8; j++)
#pragma unroll
            for (int k = 0; k < 4; k++) acc[i][j][k] = 0.f;

    const int lrow = t >> 3;
    const int lch = t & 7;

    // prologue: stage 0
    {
#pragma unroll
        for (int j = 0; j < 4; j++) {
            int row = lrow + j * 32;
            uint32_t sa = sb + row * PITCH + lch * 16;
            size_t ga = (size_t)(m0 + row) * HID_ + lch * 8;
            size_t gb = (size_t)(n0 + row) * HID_ + lch * 8;
            cpa16(sa, AH + ga);
            cpa16(sa + MATB, AL + ga);
            cpa16(sa + 2 * MATB, BH + gb);
        }
        CP_COMMIT();
    }

    const uint32_t lm_a_off =
        (uint32_t)((wm * 32 + (lane & 15)) * PITCH + (lane >> 4) * 16);
    const uint32_t lm_b_off =
        (uint32_t)((wn * 64 + (lane & 15)) * PITCH + (lane >> 4) * 16);

    for (int c = 0; c < NCH; c++) {
        CP_WAIT0();           // load for chunk c complete
        __syncthreads();      // all warps past reads of the buffer we'll fill

        if (c + 1 < NCH) {
            const uint32_t base = sb + ((c + 1) & 1) * BUFB;
            const int k0 = (c + 1) * 64;
#pragma unroll
            for (int j = 0; j < 4; j++) {
                int row = lrow + j * 32;
                uint32_t sa = base + row * PITCH + lch * 16;
                size_t ga = (size_t)(m0 + row) * HID_ + k0 + lch * 8;
                size_t gb = (size_t)(n0 + row) * HID_ + k0 + lch * 8;
                cpa16(sa, AH + ga);
                cpa16(sa + MATB, AL + ga);
                cpa16(sa + 2 * MATB, BH + gb);
            }
            CP_COMMIT();
        }

        const uint32_t cb = sb + (c & 1) * BUFB;
#pragma unroll
        for (int ks = 0; ks < 4; ks++) {
            uint32_t ah[2][4], al[2][4];
#pragma unroll
            for (int mt = 0; mt < 2; mt++) {
                uint32_t addr = cb + lm_a_off + mt * (16 * PITCH) + ks * 32;
                LDSM4(ah[mt], addr);
                LDSM4(al[mt], addr + MATB);
            }
            uint32_t bh[8][2];
#pragma unroll
            for (int np = 0; np < 4; np++) {
                uint32_t addr = cb + 2 * MATB + lm_b_off + np * (16 * PITCH) + ks * 32;
                uint32_t r[4];
                LDSM4(r, addr);
                bh[2 * np][0] = r[0]; bh[2 * np + 1][0] = r[1];
                bh[2 * np][1] = r[2]; bh[2 * np + 1][1] = r[3];
            }
#pragma unroll
            for (int mt = 0; mt < 2; mt++)
#pragma unroll
                for (int nt = 0; nt < 8; nt++)
                    MMAF32(acc[mt][nt], ah[mt], bh[nt]);
#pragma unroll
            for (int mt = 0; mt < 2; mt++)
#pragma unroll
                for (int nt = 0; nt < 8; nt++)
                    MMAF32(acc[mt][nt], al[mt], bh[nt]);
        }
    }

    // Epilogue
    const int qrow = lane >> 2;
    const int qcol = (lane & 3) * 2;
#pragma unroll
    for (int mt = 0; mt < 2; mt++) {
#pragma unroll
        for (int half_ = 0; half_ < 2; half_++) {
            const int m = m0 + wm * 32 + mt * 16 + qrow + half_ * 8;
            if (MODE == 1 && widx == 2) {
                int b_ = m >> 11, s_ = m & (S_ - 1);
                size_t base = (((size_t)b_ * H_ + nblk) * S_ + s_) * D_;
#pragma unroll
                for (int nt = 0; nt < 8; nt++) {
                    int col = wn * 64 + nt * 8 + qcol;
                    *(uint32_t*)(g_vh + base + col) =
                        f2h2(acc[mt][nt][half_ * 2], acc[mt][nt][half_ * 2 + 1]);
                }
            } else {
                float* dst;
                size_t base;
                if (MODE == 0) {
                    dst = Cout;
                    base = (size_t)m * HID_ + n0;
                } else {
                    int b_ = m >> 11, s_ = m & (S_ - 1);
                    dst = (widx == 0) ? g_q : g_k;
                    base = (((size_t)b_ * H_ + nblk) * S_ + s_) * D_;
                }
#pragma unroll
                for (int nt = 0; nt < 8; nt++) {
                    int col = wn * 64 + nt * 8 + qcol;
                    *(float2*)(dst + base + col) =
                        make_float2(acc[mt][nt][half_ * 2], acc[mt][nt][half_ * 2 + 1]);
                }
            }
        }
    }
}

// ---------------------------------------------------------------------------
// RoPE: read fp32 g_q/g_k, rotate, emit qh/ql (fp16 split) and kh (round).
// ---------------------------------------------------------------------------
__global__ void rope_split_kernel(const float* __restrict__ cosb,
                                  const float* __restrict__ sinb) {
    int tid = blockIdx.x * 256 + threadIdx.x;
    int d = tid & 63;
    int s = (tid >> 6) & (S_ - 1);
    int bh = tid >> 17;
    size_t base = ((size_t)bh * S_ + s) * D_;
    float c0 = cosb[s * D_ + d], c1 = cosb[s * D_ + d + 64];
    float s0 = sinb[s * D_ + d], s1 = sinb[s * D_ + d + 64];

    float q0 = g_q[base + d], q1 = g_q[base + d + 64];
    float k0 = g_k[base + d], k1 = g_k[base + d + 64];
    float qa = q0 * c0 - q1 * s0;
    float qb = q1 * c1 + q0 * s1;
    float ka = k0 * c0 - k1 * s0;
    float kb = k1 * c1 + k0 * s1;

    unsigned short h, l;
    split1(qa, h, l);
    g_qh[base + d] = __ushort_as_half(h);
    g_ql[base + d] = __ushort_as_half(l);
    split1(qb, h, l);
    g_qh[base + d + 64] = __ushort_as_half(h);
    g_ql[base + d + 64] = __ushort_as_half(l);
    g_kh[base + d] = __float2half_rn(ka);
    g_kh[base + d + 64] = __float2half_rn(kb);
}

// ---------------------------------------------------------------------------
// Flash attention, fp16x2 mma (unchanged from R10).
// SMEM: Qh, Ql, Kh, Vh each [128][128] fp16 at 272B pitch = 136KB.
// ---------------------------------------------------------------------------
#define AP   272
#define AMAT (128 * AP)
#define ATTN_SMEM (4 * AMAT)          // 139264

__global__ __launch_bounds__(256, 1) void attn_mma_kernel() {
    extern __shared__ char sm8[];
    const uint32_t sb = smem_u32(sm8);
    const uint32_t Qh = sb,            Ql = sb + AMAT;
    const uint32_t Kh = sb + 2 * AMAT, Vh = sb + 3 * AMAT;

    const int t = threadIdx.x, lane = t & 31, wid = t >> 5;
    const int bh = blockIdx.y;
    const int q0 = blockIdx.x * 128;
    const size_t qoff = ((size_t)bh * S_ + q0) * D_;
    const size_t koff = (size_t)bh * S_ * D_;

#pragma unroll
    for (int j = 0; j < 8; j++) {
        int idx = t + j * 256;
        int row = idx >> 4, ch = idx & 15;
        uint32_t so = (uint32_t)(row * AP + ch * 16);
        size_t go = qoff + (size_t)row * D_ + ch * 8;
        cpa16(Qh + so, g_qh + go);
        cpa16(Ql + so, g_ql + go);
    }
    CP_COMMIT();

    float sa[16][4];
    float oa[16][4];
#pragma unroll
    for (int i = 0; i < 16; i++)
#pragma unroll
        for (int j = 0; j < 4; j++) oa[i][j] = 0.f;
    float m0r = -1e30f, m1r = -1e30f, l0r = 0.f, l1r = 0.f;

    const float scale = 0.088388347648318447f;
    const uint32_t a_off =
        (uint32_t)((wid * 16 + (lane & 15)) * AP + (lane >> 4) * 16);
    const uint32_t lm_lo = (uint32_t)((lane & 15) * AP + (lane >> 4) * 16);

    for (int kt = 0; kt < S_ / 128; kt++) {
        __syncthreads();
#pragma unroll
        for (int j = 0; j < 8; j++) {
            int idx = t + j * 256;
            int row = idx >> 4, ch = idx & 15;
            uint32_t so = (uint32_t)(row * AP + ch * 16);
            size_t go = koff + (size_t)(kt * 128 + row) * D_ + ch * 8;
            cpa16(Kh + so, g_kh + go);
        }
        CP_COMMIT();
#pragma unroll
        for (int j = 0; j < 8; j++) {
            int idx = t + j * 256;
            int row = idx >> 4, ch = idx & 15;
            uint32_t so = (uint32_t)(row * AP + ch * 16);
            size_t go = koff + (size_t)(kt * 128 + row) * D_ + ch * 8;
            cpa16(Vh + so, g_vh + go);
        }
        CP_COMMIT();

        CP_WAIT1();
        __syncthreads();

#pragma unroll
        for (int i = 0; i < 16; i++)
#pragma unroll
            for (int j = 0; j < 4; j++) sa[i][j] = 0.f;

#pragma unroll
        for (int ks = 0; ks < 8; ks++) {
            uint32_t qh[4], ql[4];
            LDSM4(qh, Qh + a_off + ks * 32);
            LDSM4(ql, Ql + a_off + ks * 32);
#pragma unroll
            for (int h2 = 0; h2 < 2; h2++) {
                uint32_t kA[4][2], kB[4][2];
#pragma unroll
                for (int j = 0; j < 4; j++) {
                    const int np = h2 * 4 + j;
                    uint32_t r[4];
                    LDSM4(r, Kh + lm_lo + (uint32_t)(np * 16 * AP) + ks * 32);
                    kA[j][0] = r[0]; kB[j][0] = r[1];
                    kA[j][1] = r[2]; kB[j][1] = r[3];
                }
#pragma unroll
                for (int j = 0; j < 4; j++) {
                    const int np = h2 * 4 + j;
                    MMAF32(sa[2 * np], qh, kA[j]);
                    MMAF32(sa[2 * np + 1], qh, kB[j]);
                }
#pragma unroll
                for (int j = 0; j < 4; j++) {
                    const int np = h2 * 4 + j;
                    MMAF32(sa[2 * np], ql, kA[j]);
                    MMAF32(sa[2 * np + 1], ql, kB[j]);
                }
            }
        }

        // ---- online softmax ----
        float rm0 = -1e30f, rm1 = -1e30f;
#pragma unroll
        for (int nt = 0; nt < 16; nt++) {
            rm0 = fmaxf(rm0, fmaxf(sa[nt][0], sa[nt][1]));
            rm1 = fmaxf(rm1, fmaxf(sa[nt][2], sa[nt][3]));
        }
#pragma unroll
        for (int off = 1; off <= 2; off <<= 1) {
            rm0 = fmaxf(rm0, __shfl_xor_sync(0xffffffffu, rm0, off));
            rm1 = fmaxf(rm1, __shfl_xor_sync(0xffffffffu, rm1, off));
        }
        float mn0 = fmaxf(m0r, rm0 * scale);
        float mn1 = fmaxf(m1r, rm1 * scale);
        float al0 = __expf(m0r - mn0);
        float al1 = __expf(m1r - mn1);
        m0r = mn0;
        m1r = mn1;
        float rs0 = 0.f, rs1 = 0.f;
#pragma unroll
        for (int nt = 0; nt < 16; nt++) {
            float p0 = __expf(fmaf(sa[nt][0], scale, -mn0));
            float p1 = __expf(fmaf(sa[nt][1], scale, -mn0));
            float p2 = __expf(fmaf(sa[nt][2], scale, -mn1));
            float p3 = __expf(fmaf(sa[nt][3], scale, -mn1));
            sa[nt][0] = p0; sa[nt][1] = p1; sa[nt][2] = p2; sa[nt][3] = p3;
            rs0 += p0 + p1;
            rs1 += p2 + p3;
        }
#pragma unroll
        for (int off = 1; off <= 2; off <<= 1) {
            rs0 += __shfl_xor_sync(0xffffffffu, rs0, off);
            rs1 += __shfl_xor_sync(0xffffffffu, rs1, off);
        }
        l0r = l0r * al0 + rs0;
        l1r = l1r * al1 + rs1;
#pragma unroll
        for (int nt = 0; nt < 16; nt++) {
            oa[nt][0] *= al0;
            oa[nt][1] *= al0;
            oa[nt][2] *= al1;
            oa[nt][3] *= al1;
        }

        CP_WAIT0();
        __syncthreads();

        // ---- O += P V ----
#pragma unroll
        for (int ks = 0; ks < 8; ks++) {
            uint32_t aH[4], aL[4];
#pragma unroll
            for (int g = 0; g < 2; g++) {
                const int tt = 2 * ks + g;
                float x0 = sa[tt][0], y0 = sa[tt][1];
                float x1 = sa[tt][2], y1 = sa[tt][3];
                uint32_t h0 = f2h2(x0, y0);
                uint32_t h1 = f2h2(x1, y1);
                float2 b0 = h2f2(h0);
                float2 b1 = h2f2(h1);
                aH[2 * g]     = h0;
                aH[2 * g + 1] = h1;
                aL[2 * g]     = f2h2(x0 - b0.x, y0 - b0.y);
                aL[2 * g + 1] = f2h2(x1 - b1.x, y1 - b1.y);
            }
            const uint32_t vbase = lm_lo + (uint32_t)(ks * 16 * AP);
#pragma unroll
            for (int h2 = 0; h2 < 2; h2++) {
                uint32_t vA[4][2], vB[4][2];
#pragma unroll
                for (int j = 0; j < 4; j++) {
                    const int np = h2 * 4 + j;
                    uint32_t r[4];
                    LDSM4T(r, Vh + vbase + np * 32);
                    vA[j][0] = r[0]; vA[j][1] = r[1];
                    vB[j][0] = r[2]; vB[j][1] = r[3];
                }
#pragma unroll
                for (int j = 0; j < 4; j++) {
                    const int np = h2 * 4 + j;
                    MMAF32(oa[2 * np], aH, vA[j]);
                    MMAF32(oa[2 * np + 1], aH, vB[j]);
                }
#pragma unroll
                for (int j = 0; j < 4; j++) {
                    const int np = h2 * 4 + j;
                    MMAF32(oa[2 * np], aL, vA[j]);
                    MMAF32(oa[2 * np + 1], aL, vB[j]);
                }
            }
        }
    }

    // ---- finalize: write xhi/xlo fp16 splits of attn output directly ----
    const int b_ = bh >> 4, h = bh & 15;
    const int row0 = q0 + wid * 16 + (lane >> 2);
    const float inv0 = 1.0f / l0r, inv1 = 1.0f / l1r;
    const size_t base0 = ((size_t)b_ * S_ + row0) * HID_ + h * D_;
    const size_t base1 = ((size_t)b_ * S_ + row0 + 8) * HID_ + h * D_;
    const int col0 = (lane & 3) * 2;
#pragma unroll
    for (int nt = 0; nt < 16; nt++) {
        int col = 8 * nt + col0;
        float x0 = oa[nt][0] * inv0, y0 = oa[nt][1] * inv0;
        float x1 = oa[nt][2] * inv1, y1 = oa[nt][3] * inv1;
        unsigned short hx, lx, hy, ly;
        split1(x0, hx, lx);
        split1(y0, hy, ly);
        *(uint32_t*)(g_xhi + base0 + col) = (uint32_t)hx | ((uint32_t)hy << 16);
        *(uint32_t*)(g_xlo + base0 + col) = (uint32_t)lx | ((uint32_t)ly << 16);
        split1(x1, hx, lx);
        split1(y1, hy, ly);
        *(uint32_t*)(g_xhi + base1 + col) = (uint32_t)hx | ((uint32_t)hy << 16);
        *(uint32_t*)(g_xlo + base1 + col) = (uint32_t)lx | ((uint32_t)ly << 16);
    }
}

// ---------------------------------------------------------------------------
// Launch
// ---------------------------------------------------------------------------
extern "C" void kernel_launch(void* const* d_in, const int* in_sizes, int n_in,
                              void* d_out, int out_size) {
    const float* X = (const float*)d_in[0];
    const float* cosb = (const float*)d_in[1];
    const float* sinb = (const float*)d_in[2];
    const float* Wq = (const float*)d_in[3];
    const float* Wk = (const float*)d_in[4];
    const float* Wv = (const float*)d_in[5];
    const float* Wo = (const float*)d_in[6];
    float* out = (float*)d_out;

    cudaFuncSetAttribute(mma_gemm<0>, cudaFuncAttributeMaxDynamicSharedMemorySize, GEMM_SMEM);
    cudaFuncSetAttribute(mma_gemm<1>, cudaFuncAttributeMaxDynamicSharedMemorySize, GEMM_SMEM);
    cudaFuncSetAttribute(attn_mma_kernel, cudaFuncAttributeMaxDynamicSharedMemorySize, ATTN_SMEM);

    // all weight conversions in one launch; activations split
    wsplit_kernel<<<dim3(64, 64, 4), dim3(32, 8)>>>(Wq, Wk, Wv, Wo);
    asplit_kernel<<<(M_ * HID_ / 4) / 256, 256>>>(X);

    // fused QKV projection
    mma_gemm<1><<<dim3(48, M_ / 128), 256, GEMM_SMEM>>>(nullptr);

    rope_split_kernel<<<(B_ * H_ * S_ * 64) / 256, 256>>>(cosb, sinb);

    // attention writes g_xhi/g_xlo directly
    attn_mma_kernel<<<dim3(S_ / 128, B_ * H_), 256, ATTN_SMEM>>>();

    // O projection
    mma_gemm<0><<<dim3(HID_ / 128, M_ / 128), 256, GEMM_SMEM>>>(out);
}

// round 12
// speedup vs baseline: 1.7098x; 1.0111x over previous
#include <cuda_runtime.h>
#include <cuda_fp16.h>
#include <cstdint>

// ---------------------------------------------------------------------------
// Problem constants
// ---------------------------------------------------------------------------
#define B_ 2
#define S_ 2048
#define H_ 16
#define D_ 128
#define HID_ 2048
#define M_ (B_ * S_)   // 4096

// Scratch (device globals — allocation-free per harness rules)
__device__ float g_q[(size_t)B_ * H_ * S_ * D_];   // fp32 Q pre-rope [b,h,s,d]
__device__ float g_k[(size_t)B_ * H_ * S_ * D_];   // fp32 K pre-rope

// fp16 buffers. Activations split hi/lo; weights hi only (2-term emulation).
__device__ __half g_xhi[(size_t)M_ * HID_];
__device__ __half g_xlo[(size_t)M_ * HID_];
__device__ __half g_bhi[(size_t)4 * HID_ * HID_];

// fp16 attention operands [b,h,s,d]: Q split hi/lo; K, V hi only.
#define QKV_ELEMS ((size_t)B_ * H_ * S_ * D_)
__device__ __half g_qh[QKV_ELEMS];
__device__ __half g_ql[QKV_ELEMS];
__device__ __half g_kh[QKV_ELEMS];
__device__ __half g_vh[QKV_ELEMS];

// ---------------------------------------------------------------------------
// PTX helpers (non-'a' features only)
// ---------------------------------------------------------------------------
__device__ __forceinline__ uint32_t smem_u32(const void* p) {
    uint32_t a;
    asm("{ .reg .u64 t; cvta.to.shared.u64 t, %1; cvt.u32.u64 %0, t; }"
        : "=r"(a) : "l"(p));
    return a;
}
__device__ __forceinline__ void cpa16(uint32_t s, const void* g) {
    asm volatile("cp.async.cg.shared.global [%0], [%1], 16;" :: "r"(s), "l"(g));
}
#define CP_COMMIT() asm volatile("cp.async.commit_group;" ::: "memory")
#define CP_WAIT0()  asm volatile("cp.async.wait_group 0;" ::: "memory")
#define CP_WAIT1()  asm volatile("cp.async.wait_group 1;" ::: "memory")

#define LDSM4(r, addr)                                                        \
    asm volatile("ldmatrix.sync.aligned.m8n8.x4.shared.b16 {%0,%1,%2,%3}, [%4];" \
                 : "=r"((r)[0]), "=r"((r)[1]), "=r"((r)[2]), "=r"((r)[3])     \
                 : "r"(addr))
#define LDSM4T(r, addr)                                                       \
    asm volatile("ldmatrix.sync.aligned.m8n8.x4.trans.shared.b16 {%0,%1,%2,%3}, [%4];" \
                 : "=r"((r)[0]), "=r"((r)[1]), "=r"((r)[2]), "=r"((r)[3])     \
                 : "r"(addr))

#define MMAF32(d, a, b)                                                       \
    asm volatile(                                                             \
        "mma.sync.aligned.m16n8k16.row.col.f32.f16.f16.f32 "                  \
        "{%0,%1,%2,%3}, {%4,%5,%6,%7}, {%8,%9}, {%0,%1,%2,%3};"               \
        : "+f"((d)[0]), "+f"((d)[1]), "+f"((d)[2]), "+f"((d)[3])              \
        : "r"((a)[0]), "r"((a)[1]), "r"((a)[2]), "r"((a)[3]),                 \
          "r"((b)[0]), "r"((b)[1]))

__device__ __forceinline__ float2 h2f2(uint32_t u) {
    __half2 h = *(__half2*)&u;
    return __half22float2(h);
}
__device__ __forceinline__ uint32_t f2h2(float x, float y) {
    __half2 h = __float22half2_rn(make_float2(x, y));
    return *(uint32_t*)&h;
}

// fp32 -> fp16 hi/lo split
__device__ __forceinline__ void split1(float x, unsigned short& h, unsigned short& l) {
    __half hb = __float2half_rn(x);
    __half lb = __float2half_rn(x - __half2float(hb));
    h = __half_as_ushort(hb);
    l = __half_as_ushort(lb);
}

// ---------------------------------------------------------------------------
// Activations: X [M,K] fp32 -> g_xhi/g_xlo fp16.
// ---------------------------------------------------------------------------
__global__ void asplit_kernel(const float* __restrict__ src) {
    size_t i = (size_t)blockIdx.x * 256 + threadIdx.x;
    float4 v = ((const float4*)src)[i];
    ushort4 h, l;
    split1(v.x, h.x, l.x);
    split1(v.y, h.y, l.y);
    split1(v.z, h.z, l.z);
    split1(v.w, h.w, l.w);
    ((ushort4*)g_xhi)[i] = h;
    ((ushort4*)g_xlo)[i] = l;
}

// All 4 weights in one launch: W [K,N] fp32 -> g_bhi slot z, [N,K] fp16 hi.
__global__ void wsplit_kernel(const float* __restrict__ W0,
                              const float* __restrict__ W1,
                              const float* __restrict__ W2,
                              const float* __restrict__ W3) {
    __shared__ float ts[32][33];
    const int tx = threadIdx.x, ty = threadIdx.y;
    const int n0 = blockIdx.x * 32, k0 = blockIdx.y * 32;
    const int widx = blockIdx.z;
    const float* W = (widx == 0) ? W0 : (widx == 1) ? W1 : (widx == 2) ? W2 : W3;
    __half* bh = g_bhi + (size_t)widx * HID_ * HID_;
#pragma unroll
    for (int i = 0; i < 4; i++)
        ts[ty + 8 * i][tx] = W[(size_t)(k0 + ty + 8 * i) * HID_ + n0 + tx];
    __syncthreads();
#pragma unroll
    for (int i = 0; i < 4; i++) {
        int n = n0 + ty + 8 * i;
        int k = k0 + tx;
        bh[(size_t)n * HID_ + k] = __float2half_rn(ts[tx][ty + 8 * i]);
    }
}

// ---------------------------------------------------------------------------
// mma.sync fp16x2 GEMM (Ah*Bh + Al*Bh, both f32-accum).
// 2-stage double buffer, 2 CTAs/SM (unchanged from R11 — proven win).
// MODE==1: fused QKV (blockIdx.x = widx*16 + head). MODE==0: O projection.
// ---------------------------------------------------------------------------
#define PITCH 144
#define MATB  (128 * PITCH)          // 18432
#define BUFB  (3 * MATB)             // 55296 (Ah, Al, Bh)
#define GEMM_SMEM (2 * BUFB)         // 110592 -> two CTAs fit per SM
#define NCH (HID_ / 64)              // 32

template <int MODE>
__global__ __launch_bounds__(256, 2) void mma_gemm(float* __restrict__ Cout) {
    extern __shared__ char dsm[];
    const uint32_t sb = smem_u32(dsm);
    const int t = threadIdx.x;
    const int lane = t & 31, wid = t >> 5;
    const int wm = wid & 3, wn = wid >> 2;
    const int m0 = blockIdx.y * 128;
    const int widx = (MODE == 1) ? (blockIdx.x >> 4) : 3;
    const int nblk = (MODE == 1) ? (blockIdx.x & 15) : blockIdx.x;
    const int n0 = nblk * 128;

    const __half* __restrict__ AH = g_xhi;
    const __half* __restrict__ AL = g_xlo;
    const __half* __restrict__ BH = g_bhi + (size_t)widx * HID_ * HID_;

    float acc[2][8][4];
#pragma unroll
    for (int i = 0; i < 2; i++)
#pragma unroll
        for (int j = 0; j < 8; j++)
#pragma unroll
            for (int k = 0; k < 4; k++) acc[i][j][k] = 0.f;

    const int lrow = t >> 3;
    const int lch = t & 7;

    // prologue: stage 0
    {
#pragma unroll
        for (int j = 0; j < 4; j++) {
            int row = lrow + j * 32;
            uint32_t sa = sb + row * PITCH + lch * 16;
            size_t ga = (size_t)(m0 + row) * HID_ + lch * 8;
            size_t gb = (size_t)(n0 + row) * HID_ + lch * 8;
            cpa16(sa, AH + ga);
            cpa16(sa + MATB, AL + ga);
            cpa16(sa + 2 * MATB, BH + gb);
        }
        CP_COMMIT();
    }

    const uint32_t lm_a_off =
        (uint32_t)((wm * 32 + (lane & 15)) * PITCH + (lane >> 4) * 16);
    const uint32_t lm_b_off =
        (uint32_t)((wn * 64 + (lane & 15)) * PITCH + (lane >> 4) * 16);

    for (int c = 0; c < NCH; c++) {
        CP_WAIT0();
        __syncthreads();

        if (c + 1 < NCH) {
            const uint32_t base = sb + ((c + 1) & 1) * BUFB;
            const int k0 = (c + 1) * 64;
#pragma unroll
            for (int j = 0; j < 4; j++) {
                int row = lrow + j * 32;
                uint32_t sa = base + row * PITCH + lch * 16;
                size_t ga = (size_t)(m0 + row) * HID_ + k0 + lch * 8;
                size_t gb = (size_t)(n0 + row) * HID_ + k0 + lch * 8;
                cpa16(sa, AH + ga);
                cpa16(sa + MATB, AL + ga);
                cpa16(sa + 2 * MATB, BH + gb);
            }
            CP_COMMIT();
        }

        const uint32_t cb = sb + (c & 1) * BUFB;
#pragma unroll
        for (int ks = 0; ks < 4; ks++) {
            uint32_t ah[2][4], al[2][4];
#pragma unroll
            for (int mt = 0; mt < 2; mt++) {
                uint32_t addr = cb + lm_a_off + mt * (16 * PITCH) + ks * 32;
                LDSM4(ah[mt], addr);
                LDSM4(al[mt], addr + MATB);
            }
            uint32_t bh[8][2];
#pragma unroll
            for (int np = 0; np < 4; np++) {
                uint32_t addr = cb + 2 * MATB + lm_b_off + np * (16 * PITCH) + ks * 32;
                uint32_t r[4];
                LDSM4(r, addr);
                bh[2 * np][0] = r[0]; bh[2 * np + 1][0] = r[1];
                bh[2 * np][1] = r[2]; bh[2 * np + 1][1] = r[3];
            }
#pragma unroll
            for (int mt = 0; mt < 2; mt++)
#pragma unroll
                for (int nt = 0; nt < 8; nt++)
                    MMAF32(acc[mt][nt], ah[mt], bh[nt]);
#pragma unroll
            for (int mt = 0; mt < 2; mt++)
#pragma unroll
                for (int nt = 0; nt < 8; nt++)
                    MMAF32(acc[mt][nt], al[mt], bh[nt]);
        }
    }

    // Epilogue
    const int qrow = lane >> 2;
    const int qcol = (lane & 3) * 2;
#pragma unroll
    for (int mt = 0; mt < 2; mt++) {
#pragma unroll
        for (int half_ = 0; half_ < 2; half_++) {
            const int m = m0 + wm * 32 + mt * 16 + qrow + half_ * 8;
            if (MODE == 1 && widx == 2) {
                int b_ = m >> 11, s_ = m & (S_ - 1);
                size_t base = (((size_t)b_ * H_ + nblk) * S_ + s_) * D_;
#pragma unroll
                for (int nt = 0; nt < 8; nt++) {
                    int col = wn * 64 + nt * 8 + qcol;
                    *(uint32_t*)(g_vh + base + col) =
                        f2h2(acc[mt][nt][half_ * 2], acc[mt][nt][half_ * 2 + 1]);
                }
            } else {
                float* dst;
                size_t base;
                if (MODE == 0) {
                    dst = Cout;
                    base = (size_t)m * HID_ + n0;
                } else {
                    int b_ = m >> 11, s_ = m & (S_ - 1);
                    dst = (widx == 0) ? g_q : g_k;
                    base = (((size_t)b_ * H_ + nblk) * S_ + s_) * D_;
                }
#pragma unroll
                for (int nt = 0; nt < 8; nt++) {
                    int col = wn * 64 + nt * 8 + qcol;
                    *(float2*)(dst + base + col) =
                        make_float2(acc[mt][nt][half_ * 2], acc[mt][nt][half_ * 2 + 1]);
                }
            }
        }
    }
}

// ---------------------------------------------------------------------------
// RoPE: read fp32 g_q/g_k, rotate, emit qh/ql (fp16 split) and kh (round).
// ---------------------------------------------------------------------------
__global__ void rope_split_kernel(const float* __restrict__ cosb,
                                  const float* __restrict__ sinb) {
    int tid = blockIdx.x * 256 + threadIdx.x;
    int d = tid & 63;
    int s = (tid >> 6) & (S_ - 1);
    int bh = tid >> 17;
    size_t base = ((size_t)bh * S_ + s) * D_;
    float c0 = cosb[s * D_ + d], c1 = cosb[s * D_ + d + 64];
    float s0 = sinb[s * D_ + d], s1 = sinb[s * D_ + d + 64];

    float q0 = g_q[base + d], q1 = g_q[base + d + 64];
    float k0 = g_k[base + d], k1 = g_k[base + d + 64];
    float qa = q0 * c0 - q1 * s0;
    float qb = q1 * c1 + q0 * s1;
    float ka = k0 * c0 - k1 * s0;
    float kb = k1 * c1 + k0 * s1;

    unsigned short h, l;
    split1(qa, h, l);
    g_qh[base + d] = __ushort_as_half(h);
    g_ql[base + d] = __ushort_as_half(l);
    split1(qb, h, l);
    g_qh[base + d + 64] = __ushort_as_half(h);
    g_ql[base + d + 64] = __ushort_as_half(l);
    g_kh[base + d] = __float2half_rn(ka);
    g_kh[base + d + 64] = __float2half_rn(kb);
}

// ---------------------------------------------------------------------------
// Flash attention, fp16x2 mma; K/V double-buffered, prefetched one tile ahead
// so the 128KB/tile load is hidden behind the previous tile's mma work.
// SMEM: Qh, Ql, Kh[2], Vh[2] each [128][128] fp16 at 272B pitch = 204KB.
// Epilogue writes g_xhi/g_xlo splits directly (feeds O-projection).
// ---------------------------------------------------------------------------
#define AP   272
#define AMAT (128 * AP)
#define ATTN_SMEM (6 * AMAT)          // 208896

__global__ __launch_bounds__(256, 1) void attn_mma_kernel() {
    extern __shared__ char sm8[];
    const uint32_t sb = smem_u32(sm8);
    const uint32_t Qh = sb, Ql = sb + AMAT;
    // Kh buf at sb + (2 + buf)*AMAT, Vh buf at sb + (4 + buf)*AMAT

    const int t = threadIdx.x, lane = t & 31, wid = t >> 5;
    const int bh = blockIdx.y;
    const int q0 = blockIdx.x * 128;
    const size_t qoff = ((size_t)bh * S_ + q0) * D_;
    const size_t koff = (size_t)bh * S_ * D_;

    const int lrow = t >> 4;           // 0..15 (x16 = 0..127 with j)
    const int lch = t & 15;

    // prologue: Q + K0 + V0 in ONE group
    {
        const uint32_t K0 = sb + 2 * AMAT, V0 = sb + 4 * AMAT;
#pragma unroll
        for (int j = 0; j < 8; j++) {
            int row = lrow + j * 16;
            uint32_t so = (uint32_t)(row * AP + lch * 16);
            size_t gq = qoff + (size_t)row * D_ + lch * 8;
            size_t gk = koff + (size_t)row * D_ + lch * 8;
            cpa16(Qh + so, g_qh + gq);
            cpa16(Ql + so, g_ql + gq);
            cpa16(K0 + so, g_kh + gk);
            cpa16(V0 + so, g_vh + gk);
        }
        CP_COMMIT();
    }

    float sa[16][4];
    float oa[16][4];
#pragma unroll
    for (int i = 0; i < 16; i++)
#pragma unroll
        for (int j = 0; j < 4; j++) oa[i][j] = 0.f;
    float m0r = -1e30f, m1r = -1e30f, l0r = 0.f, l1r = 0.f;

    const float scale = 0.088388347648318447f;
    const uint32_t a_off =
        (uint32_t)((wid * 16 + (lane & 15)) * AP + (lane >> 4) * 16);
    const uint32_t lm_lo = (uint32_t)((lane & 15) * AP + (lane >> 4) * 16);

    for (int kt = 0; kt < S_ / 128; kt++) {
        // all warps done reading buffer (kt+1)&1 (last used in iter kt-1)
        __syncthreads();

        // prefetch tile kt+1 into the other buffer
        if (kt + 1 < S_ / 128) {
            const uint32_t Kn = sb + (2 + ((kt + 1) & 1)) * AMAT;
            const uint32_t Vn = sb + (4 + ((kt + 1) & 1)) * AMAT;
#pragma unroll
            for (int j = 0; j < 8; j++) {
                int row = lrow + j * 16;
                uint32_t so = (uint32_t)(row * AP + lch * 16);
                size_t gk = koff + (size_t)((kt + 1) * 128 + row) * D_ + lch * 8;
                cpa16(Kn + so, g_kh + gk);
                cpa16(Vn + so, g_vh + gk);
            }
        }
        CP_COMMIT();          // possibly-empty group keeps accounting uniform

        CP_WAIT1();           // current tile (committed last iter / prologue) done
        __syncthreads();      // make other threads' copies visible

        const uint32_t Kc = sb + (2 + (kt & 1)) * AMAT;
        const uint32_t Vc = sb + (4 + (kt & 1)) * AMAT;

#pragma unroll
        for (int i = 0; i < 16; i++)
#pragma unroll
            for (int j = 0; j < 4; j++) sa[i][j] = 0.f;

        // ---- S = Q K^T ----
#pragma unroll
        for (int ks = 0; ks < 8; ks++) {
            uint32_t qh[4], ql[4];
            LDSM4(qh, Qh + a_off + ks * 32);
            LDSM4(ql, Ql + a_off + ks * 32);
#pragma unroll
            for (int h2 = 0; h2 < 2; h2++) {
                uint32_t kA[4][2], kB[4][2];
#pragma unroll
                for (int j = 0; j < 4; j++) {
                    const int np = h2 * 4 + j;
                    uint32_t r[4];
                    LDSM4(r, Kc + lm_lo + (uint32_t)(np * 16 * AP) + ks * 32);
                    kA[j][0] = r[0]; kB[j][0] = r[1];
                    kA[j][1] = r[2]; kB[j][1] = r[3];
                }
#pragma unroll
                for (int j = 0; j < 4; j++) {
                    const int np = h2 * 4 + j;
                    MMAF32(sa[2 * np], qh, kA[j]);
                    MMAF32(sa[2 * np + 1], qh, kB[j]);
                }
#pragma unroll
                for (int j = 0; j < 4; j++) {
                    const int np = h2 * 4 + j;
                    MMAF32(sa[2 * np], ql, kA[j]);
                    MMAF32(sa[2 * np + 1], ql, kB[j]);
                }
            }
        }

        // ---- online softmax ----
        float rm0 = -1e30f, rm1 = -1e30f;
#pragma unroll
        for (int nt = 0; nt < 16; nt++) {
            rm0 = fmaxf(rm0, fmaxf(sa[nt][0], sa[nt][1]));
            rm1 = fmaxf(rm1, fmaxf(sa[nt][2], sa[nt][3]));
        }
#pragma unroll
        for (int off = 1; off <= 2; off <<= 1) {
            rm0 = fmaxf(rm0, __shfl_xor_sync(0xffffffffu, rm0, off));
            rm1 = fmaxf(rm1, __shfl_xor_sync(0xffffffffu, rm1, off));
        }
        float mn0 = fmaxf(m0r, rm0 * scale);
        float mn1 = fmaxf(m1r, rm1 * scale);
        float al0 = __expf(m0r - mn0);
        float al1 = __expf(m1r - mn1);
        m0r = mn0;
        m1r = mn1;
        float rs0 = 0.f, rs1 = 0.f;
#pragma unroll
        for (int nt = 0; nt < 16; nt++) {
            float p0 = __expf(fmaf(sa[nt][0], scale, -mn0));
            float p1 = __expf(fmaf(sa[nt][1], scale, -mn0));
            float p2 = __expf(fmaf(sa[nt][2], scale, -mn1));
            float p3 = __expf(fmaf(sa[nt][3], scale, -mn1));
            sa[nt][0] = p0; sa[nt][1] = p1; sa[nt][2] = p2; sa[nt][3] = p3;
            rs0 += p0 + p1;
            rs1 += p2 + p3;
        }
#pragma unroll
        for (int off = 1; off <= 2; off <<= 1) {
            rs0 += __shfl_xor_sync(0xffffffffu, rs0, off);
            rs1 += __shfl_xor_sync(0xffffffffu, rs1, off);
        }
        l0r = l0r * al0 + rs0;
        l1r = l1r * al1 + rs1;
#pragma unroll
        for (int nt = 0; nt < 16; nt++) {
            oa[nt][0] *= al0;
            oa[nt][1] *= al0;
            oa[nt][2] *= al1;
            oa[nt][3] *= al1;
        }

        // ---- O += P V ----
#pragma unroll
        for (int ks = 0; ks < 8; ks++) {
            uint32_t aH[4], aL[4];
#pragma unroll
            for (int g = 0; g < 2; g++) {
                const int tt = 2 * ks + g;
                float x0 = sa[tt][0], y0 = sa[tt][1];
                float x1 = sa[tt][2], y1 = sa[tt][3];
                uint32_t h0 = f2h2(x0, y0);
                uint32_t h1 = f2h2(x1, y1);
                float2 b0 = h2f2(h0);
                float2 b1 = h2f2(h1);
                aH[2 * g]     = h0;
                aH[2 * g + 1] = h1;
                aL[2 * g]     = f2h2(x0 - b0.x, y0 - b0.y);
                aL[2 * g + 1] = f2h2(x1 - b1.x, y1 - b1.y);
            }
            const uint32_t vbase = lm_lo + (uint32_t)(ks * 16 * AP);
#pragma unroll
            for (int h2 = 0; h2 < 2; h2++) {
                uint32_t vA[4][2], vB[4][2];
#pragma unroll
                for (int j = 0; j < 4; j++) {
                    const int np = h2 * 4 + j;
                    uint32_t r[4];
                    LDSM4T(r, Vc + vbase + np * 32);
                    vA[j][0] = r[0]; vA[j][1] = r[1];
                    vB[j][0] = r[2]; vB[j][1] = r[3];
                }
#pragma unroll
                for (int j = 0; j < 4; j++) {
                    const int np = h2 * 4 + j;
                    MMAF32(oa[2 * np], aH, vA[j]);
                    MMAF32(oa[2 * np + 1], aH, vB[j]);
                }
#pragma unroll
                for (int j = 0; j < 4; j++) {
                    const int np = h2 * 4 + j;
                    MMAF32(oa[2 * np], aL, vA[j]);
                    MMAF32(oa[2 * np + 1], aL, vB[j]);
                }
            }
        }
    }

    // ---- finalize: write xhi/xlo fp16 splits of attn output directly ----
    const int b_ = bh >> 4, h = bh & 15;
    const int row0 = q0 + wid * 16 + (lane >> 2);
    const float inv0 = 1.0f / l0r, inv1 = 1.0f / l1r;
    const size_t base0 = ((size_t)b_ * S_ + row0) * HID_ + h * D_;
    const size_t base1 = ((size_t)b_ * S_ + row0 + 8) * HID_ + h * D_;
    const int col0 = (lane & 3) * 2;
#pragma unroll
    for (int nt = 0; nt < 16; nt++) {
        int col = 8 * nt + col0;
        float x0 = oa[nt][0] * inv0, y0 = oa[nt][1] * inv0;
        float x1 = oa[nt][2] * inv1, y1 = oa[nt][3] * inv1;
        unsigned short hx, lx, hy, ly;
        split1(x0, hx, lx);
        split1(y0, hy, ly);
        *(uint32_t*)(g_xhi + base0 + col) = (uint32_t)hx | ((uint32_t)hy << 16);
        *(uint32_t*)(g_xlo + base0 + col) = (uint32_t)lx | ((uint32_t)ly << 16);
        split1(x1, hx, lx);
        split1(y1, hy, ly);
        *(uint32_t*)(g_xhi + base1 + col) = (uint32_t)hx | ((uint32_t)hy << 16);
        *(uint32_t*)(g_xlo + base1 + col) = (uint32_t)lx | ((uint32_t)ly << 16);
    }
}

// ---------------------------------------------------------------------------
// Launch
// ---------------------------------------------------------------------------
extern "C" void kernel_launch(void* const* d_in, const int* in_sizes, int n_in,
                              void* d_out, int out_size) {
    const float* X = (const float*)d_in[0];
    const float* cosb = (const float*)d_in[1];
    const float* sinb = (const float*)d_in[2];
    const float* Wq = (const float*)d_in[3];
    const float* Wk = (const float*)d_in[4];
    const float* Wv = (const float*)d_in[5];
    const float* Wo = (const float*)d_in[6];
    float* out = (float*)d_out;

    cudaFuncSetAttribute(mma_gemm<0>, cudaFuncAttributeMaxDynamicSharedMemorySize, GEMM_SMEM);
    cudaFuncSetAttribute(mma_gemm<1>, cudaFuncAttributeMaxDynamicSharedMemorySize, GEMM_SMEM);
    cudaFuncSetAttribute(attn_mma_kernel, cudaFuncAttributeMaxDynamicSharedMemorySize, ATTN_SMEM);

    // all weight conversions in one launch; activations split
    wsplit_kernel<<<dim3(64, 64, 4), dim3(32, 8)>>>(Wq, Wk, Wv, Wo);
    asplit_kernel<<<(M_ * HID_ / 4) / 256, 256>>>(X);

    // fused QKV projection
    mma_gemm<1><<<dim3(48, M_ / 128), 256, GEMM_SMEM>>>(nullptr);

    rope_split_kernel<<<(B_ * H_ * S_ * 64) / 256, 256>>>(cosb, sinb);

    // attention writes g_xhi/g_xlo directly
    attn_mma_kernel<<<dim3(S_ / 128, B_ * H_), 256, ATTN_SMEM>>>();

    // O projection
    mma_gemm<0><<<dim3(HID_ / 128, M_ / 128), 256, GEMM_SMEM>>>(out);
}

// round 13
// speedup vs baseline: 1.7408x; 1.0182x over previous
#include <cuda_runtime.h>
#include <cuda_fp16.h>
#include <cstdint>

// ---------------------------------------------------------------------------
// Problem constants
// ---------------------------------------------------------------------------
#define B_ 2
#define S_ 2048
#define H_ 16
#define D_ 128
#define HID_ 2048
#define M_ (B_ * S_)   // 4096

// Scratch (device globals — allocation-free per harness rules)
__device__ float g_q[(size_t)B_ * H_ * S_ * D_];   // fp32 Q pre-rope [b,h,s,d]
__device__ float g_k[(size_t)B_ * H_ * S_ * D_];   // fp32 K pre-rope

// fp16 buffers. Activations split hi/lo; weights hi only (2-term emulation).
__device__ __half g_xhi[(size_t)M_ * HID_];
__device__ __half g_xlo[(size_t)M_ * HID_];
__device__ __half g_bhi[(size_t)4 * HID_ * HID_];

// fp16 attention operands [b,h,s,d]: Q split hi/lo; K, V hi only.
#define QKV_ELEMS ((size_t)B_ * H_ * S_ * D_)
__device__ __half g_qh[QKV_ELEMS];
__device__ __half g_ql[QKV_ELEMS];
__device__ __half g_kh[QKV_ELEMS];
__device__ __half g_vh[QKV_ELEMS];

// ---------------------------------------------------------------------------
// PTX helpers (non-'a' features only)
// ---------------------------------------------------------------------------
__device__ __forceinline__ uint32_t smem_u32(const void* p) {
    uint32_t a;
    asm("{ .reg .u64 t; cvta.to.shared.u64 t, %1; cvt.u32.u64 %0, t; }"
        : "=r"(a) : "l"(p));
    return a;
}
__device__ __forceinline__ void cpa16(uint32_t s, const void* g) {
    asm volatile("cp.async.cg.shared.global [%0], [%1], 16;" :: "r"(s), "l"(g));
}
#define CP_COMMIT() asm volatile("cp.async.commit_group;" ::: "memory")
#define CP_WAIT0()  asm volatile("cp.async.wait_group 0;" ::: "memory")
#define CP_WAIT1()  asm volatile("cp.async.wait_group 1;" ::: "memory")

#define LDSM4(r, addr)                                                        \
    asm volatile("ldmatrix.sync.aligned.m8n8.x4.shared.b16 {%0,%1,%2,%3}, [%4];" \
                 : "=r"((r)[0]), "=r"((r)[1]), "=r"((r)[2]), "=r"((r)[3])     \
                 : "r"(addr))
#define LDSM4T(r, addr)                                                       \
    asm volatile("ldmatrix.sync.aligned.m8n8.x4.trans.shared.b16 {%0,%1,%2,%3}, [%4];" \
                 : "=r"((r)[0]), "=r"((r)[1]), "=r"((r)[2]), "=r"((r)[3])     \
                 : "r"(addr))

#define MMAF32(d, a, b)                                                       \
    asm volatile(                                                             \
        "mma.sync.aligned.m16n8k16.row.col.f32.f16.f16.f32 "                  \
        "{%0,%1,%2,%3}, {%4,%5,%6,%7}, {%8,%9}, {%0,%1,%2,%3};"               \
        : "+f"((d)[0]), "+f"((d)[1]), "+f"((d)[2]), "+f"((d)[3])              \
        : "r"((a)[0]), "r"((a)[1]), "r"((a)[2]), "r"((a)[3]),                 \
          "r"((b)[0]), "r"((b)[1]))

__device__ __forceinline__ float2 h2f2(uint32_t u) {
    __half2 h = *(__half2*)&u;
    return __half22float2(h);
}
__device__ __forceinline__ uint32_t f2h2(float x, float y) {
    __half2 h = __float22half2_rn(make_float2(x, y));
    return *(uint32_t*)&h;
}

// fp32 -> fp16 hi/lo split
__device__ __forceinline__ void split1(float x, unsigned short& h, unsigned short& l) {
    __half hb = __float2half_rn(x);
    __half lb = __float2half_rn(x - __half2float(hb));
    h = __half_as_ushort(hb);
    l = __half_as_ushort(lb);
}

// ---------------------------------------------------------------------------
// Activations: X [M,K] fp32 -> g_xhi/g_xlo fp16.
// ---------------------------------------------------------------------------
__global__ void asplit_kernel(const float* __restrict__ src) {
    size_t i = (size_t)blockIdx.x * 256 + threadIdx.x;
    float4 v = ((const float4*)src)[i];
    ushort4 h, l;
    split1(v.x, h.x, l.x);
    split1(v.y, h.y, l.y);
    split1(v.z, h.z, l.z);
    split1(v.w, h.w, l.w);
    ((ushort4*)g_xhi)[i] = h;
    ((ushort4*)g_xlo)[i] = l;
}

// All 4 weights in one launch: W [K,N] fp32 -> g_bhi slot z, [N,K] fp16 hi.
__global__ void wsplit_kernel(const float* __restrict__ W0,
                              const float* __restrict__ W1,
                              const float* __restrict__ W2,
                              const float* __restrict__ W3) {
    __shared__ float ts[32][33];
    const int tx = threadIdx.x, ty = threadIdx.y;
    const int n0 = blockIdx.x * 32, k0 = blockIdx.y * 32;
    const int widx = blockIdx.z;
    const float* W = (widx == 0) ? W0 : (widx == 1) ? W1 : (widx == 2) ? W2 : W3;
    __half* bh = g_bhi + (size_t)widx * HID_ * HID_;
#pragma unroll
    for (int i = 0; i < 4; i++)
        ts[ty + 8 * i][tx] = W[(size_t)(k0 + ty + 8 * i) * HID_ + n0 + tx];
    __syncthreads();
#pragma unroll
    for (int i = 0; i < 4; i++) {
        int n = n0 + ty + 8 * i;
        int k = k0 + tx;
        bh[(size_t)n * HID_ + k] = __float2half_rn(ts[tx][ty + 8 * i]);
    }
}

// ---------------------------------------------------------------------------
// mma.sync fp16x2 GEMM (unchanged from R12 — proven config).
// ---------------------------------------------------------------------------
#define PITCH 144
#define MATB  (128 * PITCH)          // 18432
#define BUFB  (3 * MATB)             // 55296 (Ah, Al, Bh)
#define GEMM_SMEM (2 * BUFB)         // 110592 -> two CTAs fit per SM
#define NCH (HID_ / 64)              // 32

template <int MODE>
__global__ __launch_bounds__(256, 2) void mma_gemm(float* __restrict__ Cout) {
    extern __shared__ char dsm[];
    const uint32_t sb = smem_u32(dsm);
    const int t = threadIdx.x;
    const int lane = t & 31, wid = t >> 5;
    const int wm = wid & 3, wn = wid >> 2;
    const int m0 = blockIdx.y * 128;
    const int widx = (MODE == 1) ? (blockIdx.x >> 4) : 3;
    const int nblk = (MODE == 1) ? (blockIdx.x & 15) : blockIdx.x;
    const int n0 = nblk * 128;

    const __half* __restrict__ AH = g_xhi;
    const __half* __restrict__ AL = g_xlo;
    const __half* __restrict__ BH = g_bhi + (size_t)widx * HID_ * HID_;

    float acc[2][8][4];
#pragma unroll
    for (int i = 0; i < 2; i++)
#pragma unroll
        for (int j = 0; j < 8; j++)
#pragma unroll
            for (int k = 0; k < 4; k++) acc[i][j][k] = 0.f;

    const int lrow = t >> 3;
    const int lch = t & 7;

    {
#pragma unroll
        for (int j = 0; j < 4; j++) {
            int row = lrow + j * 32;
            uint32_t sa = sb + row * PITCH + lch * 16;
            size_t ga = (size_t)(m0 + row) * HID_ + lch * 8;
            size_t gb = (size_t)(n0 + row) * HID_ + lch * 8;
            cpa16(sa, AH + ga);
            cpa16(sa + MATB, AL + ga);
            cpa16(sa + 2 * MATB, BH + gb);
        }
        CP_COMMIT();
    }

    const uint32_t lm_a_off =
        (uint32_t)((wm * 32 + (lane & 15)) * PITCH + (lane >> 4) * 16);
    const uint32_t lm_b_off =
        (uint32_t)((wn * 64 + (lane & 15)) * PITCH + (lane >> 4) * 16);

    for (int c = 0; c < NCH; c++) {
        CP_WAIT0();
        __syncthreads();

        if (c + 1 < NCH) {
            const uint32_t base = sb + ((c + 1) & 1) * BUFB;
            const int k0 = (c + 1) * 64;
#pragma unroll
            for (int j = 0; j < 4; j++) {
                int row = lrow + j * 32;
                uint32_t sa = base + row * PITCH + lch * 16;
                size_t ga = (size_t)(m0 + row) * HID_ + k0 + lch * 8;
                size_t gb = (size_t)(n0 + row) * HID_ + k0 + lch * 8;
                cpa16(sa, AH + ga);
                cpa16(sa + MATB, AL + ga);
                cpa16(sa + 2 * MATB, BH + gb);
            }
            CP_COMMIT();
        }

        const uint32_t cb = sb + (c & 1) * BUFB;
#pragma unroll
        for (int ks = 0; ks < 4; ks++) {
            uint32_t ah[2][4], al[2][4];
#pragma unroll
            for (int mt = 0; mt < 2; mt++) {
                uint32_t addr = cb + lm_a_off + mt * (16 * PITCH) + ks * 32;
                LDSM4(ah[mt], addr);
                LDSM4(al[mt], addr + MATB);
            }
            uint32_t bh[8][2];
#pragma unroll
            for (int np = 0; np < 4; np++) {
                uint32_t addr = cb + 2 * MATB + lm_b_off + np * (16 * PITCH) + ks * 32;
                uint32_t r[4];
                LDSM4(r, addr);
                bh[2 * np][0] = r[0]; bh[2 * np + 1][0] = r[1];
                bh[2 * np][1] = r[2]; bh[2 * np + 1][1] = r[3];
            }
#pragma unroll
            for (int mt = 0; mt < 2; mt++)
#pragma unroll
                for (int nt = 0; nt < 8; nt++)
                    MMAF32(acc[mt][nt], ah[mt], bh[nt]);
#pragma unroll
            for (int mt = 0; mt < 2; mt++)
#pragma unroll
                for (int nt = 0; nt < 8; nt++)
                    MMAF32(acc[mt][nt], al[mt], bh[nt]);
        }
    }

    const int qrow = lane >> 2;
    const int qcol = (lane & 3) * 2;
#pragma unroll
    for (int mt = 0; mt < 2; mt++) {
#pragma unroll
        for (int half_ = 0; half_ < 2; half_++) {
            const int m = m0 + wm * 32 + mt * 16 + qrow + half_ * 8;
            if (MODE == 1 && widx == 2) {
                int b_ = m >> 11, s_ = m & (S_ - 1);
                size_t base = (((size_t)b_ * H_ + nblk) * S_ + s_) * D_;
#pragma unroll
                for (int nt = 0; nt < 8; nt++) {
                    int col = wn * 64 + nt * 8 + qcol;
                    *(uint32_t*)(g_vh + base + col) =
                        f2h2(acc[mt][nt][half_ * 2], acc[mt][nt][half_ * 2 + 1]);
                }
            } else {
                float* dst;
                size_t base;
                if (MODE == 0) {
                    dst = Cout;
                    base = (size_t)m * HID_ + n0;
                } else {
                    int b_ = m >> 11, s_ = m & (S_ - 1);
                    dst = (widx == 0) ? g_q : g_k;
                    base = (((size_t)b_ * H_ + nblk) * S_ + s_) * D_;
                }
#pragma unroll
                for (int nt = 0; nt < 8; nt++) {
                    int col = wn * 64 + nt * 8 + qcol;
                    *(float2*)(dst + base + col) =
                        make_float2(acc[mt][nt][half_ * 2], acc[mt][nt][half_ * 2 + 1]);
                }
            }
        }
    }
}

// ---------------------------------------------------------------------------
// RoPE: read fp32 g_q/g_k, rotate, emit qh/ql (fp16 split) and kh (round).
// ---------------------------------------------------------------------------
__global__ void rope_split_kernel(const float* __restrict__ cosb,
                                  const float* __restrict__ sinb) {
    int tid = blockIdx.x * 256 + threadIdx.x;
    int d = tid & 63;
    int s = (tid >> 6) & (S_ - 1);
    int bh = tid >> 17;
    size_t base = ((size_t)bh * S_ + s) * D_;
    float c0 = cosb[s * D_ + d], c1 = cosb[s * D_ + d + 64];
    float s0 = sinb[s * D_ + d], s1 = sinb[s * D_ + d + 64];

    float q0 = g_q[base + d], q1 = g_q[base + d + 64];
    float k0 = g_k[base + d], k1 = g_k[base + d + 64];
    float qa = q0 * c0 - q1 * s0;
    float qb = q1 * c1 + q0 * s1;
    float ka = k0 * c0 - k1 * s0;
    float kb = k1 * c1 + k0 * s1;

    unsigned short h, l;
    split1(qa, h, l);
    g_qh[base + d] = __ushort_as_half(h);
    g_ql[base + d] = __ushort_as_half(l);
    split1(qb, h, l);
    g_qh[base + d + 64] = __ushort_as_half(h);
    g_ql[base + d + 64] = __ushort_as_half(l);
    g_kh[base + d] = __float2half_rn(ka);
    g_kh[base + d + 64] = __float2half_rn(kb);
}

// ---------------------------------------------------------------------------
// Flash attention, fp16x2 mma. CTA = 64 q-rows, 128 threads (4 warps x 16
// rows), K/V in 64-key tiles, double-buffered, 2 CTAs/SM. Co-resident CTA
// has independent barriers -> its mma covers this CTA's softmax phase.
// SMEM: Qh,Ql (64x272) + Kh[2],Vh[2] (64x272 each) = 102KB.
// ---------------------------------------------------------------------------
#define AP    272
#define AMAT2 (64 * AP)               // 17408
#define ATTN_SMEM (6 * AMAT2)         // 104448
#define KT_   64                      // keys per tile
#define NKT   (S_ / KT_)              // 32 tiles

__global__ __launch_bounds__(128, 2) void attn_mma_kernel() {
    extern __shared__ char sm8[];
    const uint32_t sb = smem_u32(sm8);
    const uint32_t Qh = sb, Ql = sb + AMAT2;
    // K buf: sb + (2+buf)*AMAT2 ; V buf: sb + (4+buf)*AMAT2

    const int t = threadIdx.x, lane = t & 31, wid = t >> 5;   // 4 warps
    const int bh = blockIdx.y;
    const int q0 = blockIdx.x * 64;
    const size_t qoff = ((size_t)bh * S_ + q0) * D_;
    const size_t koff = (size_t)bh * S_ * D_;

    const int lrow = t >> 4;          // 0..7
    const int lch = t & 15;           // 0..15

    // prologue: Q(hi,lo) + K0 + V0 in ONE group
    {
        const uint32_t K0 = sb + 2 * AMAT2, V0 = sb + 4 * AMAT2;
#pragma unroll
        for (int j = 0; j < 8; j++) {
            int row = lrow + j * 8;   // 0..63
            uint32_t so = (uint32_t)(row * AP + lch * 16);
            size_t gq = qoff + (size_t)row * D_ + lch * 8;
            size_t gk = koff + (size_t)row * D_ + lch * 8;
            cpa16(Qh + so, g_qh + gq);
            cpa16(Ql + so, g_ql + gq);
            cpa16(K0 + so, g_kh + gk);
            cpa16(V0 + so, g_vh + gk);
        }
        CP_COMMIT();
    }

    float sa[8][4];                   // S tiles: 8 (64 keys)
    float oa[16][4];                  // O tiles: 16 (128 d)
#pragma unroll
    for (int i = 0; i < 16; i++)
#pragma unroll
        for (int j = 0; j < 4; j++) oa[i][j] = 0.f;
    float m0r = -1e30f, m1r = -1e30f, l0r = 0.f, l1r = 0.f;

    const float scale = 0.088388347648318447f;
    const uint32_t a_off =
        (uint32_t)((wid * 16 + (lane & 15)) * AP + (lane >> 4) * 16);
    const uint32_t lm_lo = (uint32_t)((lane & 15) * AP + (lane >> 4) * 16);

    for (int kt = 0; kt < NKT; kt++) {
        __syncthreads();              // all warps done with buffer (kt+1)&1

        // prefetch tile kt+1
        if (kt + 1 < NKT) {
            const uint32_t Kn = sb + (2 + ((kt + 1) & 1)) * AMAT2;
            const uint32_t Vn = sb + (4 + ((kt + 1) & 1)) * AMAT2;
#pragma unroll
            for (int j = 0; j < 8; j++) {
                int row = lrow + j * 8;
                uint32_t so = (uint32_t)(row * AP + lch * 16);
                size_t gk = koff + (size_t)((kt + 1) * KT_ + row) * D_ + lch * 8;
                cpa16(Kn + so, g_kh + gk);
                cpa16(Vn + so, g_vh + gk);
            }
        }
        CP_COMMIT();

        CP_WAIT1();                   // current tile resident
        __syncthreads();

        const uint32_t Kc = sb + (2 + (kt & 1)) * AMAT2;
        const uint32_t Vc = sb + (4 + (kt & 1)) * AMAT2;

#pragma unroll
        for (int i = 0; i < 8; i++)
#pragma unroll
            for (int j = 0; j < 4; j++) sa[i][j] = 0.f;

        // ---- S = Q K^T (64 keys) ----
#pragma unroll
        for (int ks = 0; ks < 8; ks++) {
            uint32_t qh[4], ql[4];
            LDSM4(qh, Qh + a_off + ks * 32);
            LDSM4(ql, Ql + a_off + ks * 32);
            uint32_t kA[4][2], kB[4][2];
#pragma unroll
            for (int np = 0; np < 4; np++) {
                uint32_t r[4];
                LDSM4(r, Kc + lm_lo + (uint32_t)(np * 16 * AP) + ks * 32);
                kA[np][0] = r[0]; kB[np][0] = r[1];
                kA[np][1] = r[2]; kB[np][1] = r[3];
            }
#pragma unroll
            for (int np = 0; np < 4; np++) {
                MMAF32(sa[2 * np], qh, kA[np]);
                MMAF32(sa[2 * np + 1], qh, kB[np]);
            }
#pragma unroll
            for (int np = 0; np < 4; np++) {
                MMAF32(sa[2 * np], ql, kA[np]);
                MMAF32(sa[2 * np + 1], ql, kB[np]);
            }
        }

        // ---- online softmax (rows qrow, qrow+8) ----
        float rm0 = -1e30f, rm1 = -1e30f;
#pragma unroll
        for (int nt = 0; nt < 8; nt++) {
            rm0 = fmaxf(rm0, fmaxf(sa[nt][0], sa[nt][1]));
            rm1 = fmaxf(rm1, fmaxf(sa[nt][2], sa[nt][3]));
        }
#pragma unroll
        for (int off = 1; off <= 2; off <<= 1) {
            rm0 = fmaxf(rm0, __shfl_xor_sync(0xffffffffu, rm0, off));
            rm1 = fmaxf(rm1, __shfl_xor_sync(0xffffffffu, rm1, off));
        }
        float mn0 = fmaxf(m0r, rm0 * scale);
        float mn1 = fmaxf(m1r, rm1 * scale);
        float al0 = __expf(m0r - mn0);
        float al1 = __expf(m1r - mn1);
        m0r = mn0;
        m1r = mn1;
        float rs0 = 0.f, rs1 = 0.f;
#pragma unroll
        for (int nt = 0; nt < 8; nt++) {
            float p0 = __expf(fmaf(sa[nt][0], scale, -mn0));
            float p1 = __expf(fmaf(sa[nt][1], scale, -mn0));
            float p2 = __expf(fmaf(sa[nt][2], scale, -mn1));
            float p3 = __expf(fmaf(sa[nt][3], scale, -mn1));
            sa[nt][0] = p0; sa[nt][1] = p1; sa[nt][2] = p2; sa[nt][3] = p3;
            rs0 += p0 + p1;
            rs1 += p2 + p3;
        }
#pragma unroll
        for (int off = 1; off <= 2; off <<= 1) {
            rs0 += __shfl_xor_sync(0xffffffffu, rs0, off);
            rs1 += __shfl_xor_sync(0xffffffffu, rs1, off);
        }
        l0r = l0r * al0 + rs0;
        l1r = l1r * al1 + rs1;
#pragma unroll
        for (int nt = 0; nt < 16; nt++) {
            oa[nt][0] *= al0;
            oa[nt][1] *= al0;
            oa[nt][2] *= al1;
            oa[nt][3] *= al1;
        }

        // ---- O += P V (64 keys x 128 d) ----
#pragma unroll
        for (int ks = 0; ks < 4; ks++) {
            uint32_t aH[4], aL[4];
#pragma unroll
            for (int g = 0; g < 2; g++) {
                const int tt = 2 * ks + g;
                float x0 = sa[tt][0], y0 = sa[tt][1];
                float x1 = sa[tt][2], y1 = sa[tt][3];
                uint32_t h0 = f2h2(x0, y0);
                uint32_t h1 = f2h2(x1, y1);
                float2 b0 = h2f2(h0);
                float2 b1 = h2f2(h1);
                aH[2 * g]     = h0;
                aH[2 * g + 1] = h1;
                aL[2 * g]     = f2h2(x0 - b0.x, y0 - b0.y);
                aL[2 * g + 1] = f2h2(x1 - b1.x, y1 - b1.y);
            }
            const uint32_t vbase = lm_lo + (uint32_t)(ks * 16 * AP);
#pragma unroll
            for (int h2 = 0; h2 < 2; h2++) {
                uint32_t vA[4][2], vB[4][2];
#pragma unroll
                for (int j = 0; j < 4; j++) {
                    const int np = h2 * 4 + j;
                    uint32_t r[4];
                    LDSM4T(r, Vc + vbase + np * 32);
                    vA[j][0] = r[0]; vA[j][1] = r[1];
                    vB[j][0] = r[2]; vB[j][1] = r[3];
                }
#pragma unroll
                for (int j = 0; j < 4; j++) {
                    const int np = h2 * 4 + j;
                    MMAF32(oa[2 * np], aH, vA[j]);
                    MMAF32(oa[2 * np + 1], aH, vB[j]);
                }
#pragma unroll
                for (int j = 0; j < 4; j++) {
                    const int np = h2 * 4 + j;
                    MMAF32(oa[2 * np], aL, vA[j]);
                    MMAF32(oa[2 * np + 1], aL, vB[j]);
                }
            }
        }
    }

    // ---- finalize: write xhi/xlo fp16 splits of attn output directly ----
    const int b_ = bh >> 4, h = bh & 15;
    const int row0 = q0 + wid * 16 + (lane >> 2);
    const float inv0 = 1.0f / l0r, inv1 = 1.0f / l1r;
    const size_t base0 = ((size_t)b_ * S_ + row0) * HID_ + h * D_;
    const size_t base1 = ((size_t)b_ * S_ + row0 + 8) * HID_ + h * D_;
    const int col0 = (lane & 3) * 2;
#pragma unroll
    for (int nt = 0; nt < 16; nt++) {
        int col = 8 * nt + col0;
        float x0 = oa[nt][0] * inv0, y0 = oa[nt][1] * inv0;
        float x1 = oa[nt][2] * inv1, y1 = oa[nt][3] * inv1;
        unsigned short hx, lx, hy, ly;
        split1(x0, hx, lx);
        split1(y0, hy, ly);
        *(uint32_t*)(g_xhi + base0 + col) = (uint32_t)hx | ((uint32_t)hy << 16);
        *(uint32_t*)(g_xlo + base0 + col) = (uint32_t)lx | ((uint32_t)ly << 16);
        split1(x1, hx, lx);
        split1(y1, hy, ly);
        *(uint32_t*)(g_xhi + base1 + col) = (uint32_t)hx | ((uint32_t)hy << 16);
        *(uint32_t*)(g_xlo + base1 + col) = (uint32_t)lx | ((uint32_t)ly << 16);
    }
}

// ---------------------------------------------------------------------------
// Launch
// ---------------------------------------------------------------------------
extern "C" void kernel_launch(void* const* d_in, const int* in_sizes, int n_in,
                              void* d_out, int out_size) {
    const float* X = (const float*)d_in[0];
    const float* cosb = (const float*)d_in[1];
    const float* sinb = (const float*)d_in[2];
    const float* Wq = (const float*)d_in[3];
    const float* Wk = (const float*)d_in[4];
    const float* Wv = (const float*)d_in[5];
    const float* Wo = (const float*)d_in[6];
    float* out = (float*)d_out;

    cudaFuncSetAttribute(mma_gemm<0>, cudaFuncAttributeMaxDynamicSharedMemorySize, GEMM_SMEM);
    cudaFuncSetAttribute(mma_gemm<1>, cudaFuncAttributeMaxDynamicSharedMemorySize, GEMM_SMEM);
    cudaFuncSetAttribute(attn_mma_kernel, cudaFuncAttributeMaxDynamicSharedMemorySize, ATTN_SMEM);

    // all weight conversions in one launch; activations split
    wsplit_kernel<<<dim3(64, 64, 4), dim3(32, 8)>>>(Wq, Wk, Wv, Wo);
    asplit_kernel<<<(M_ * HID_ / 4) / 256, 256>>>(X);

    // fused QKV projection
    mma_gemm<1><<<dim3(48, M_ / 128), 256, GEMM_SMEM>>>(nullptr);

    rope_split_kernel<<<(B_ * H_ * S_ * 64) / 256, 256>>>(cosb, sinb);

    // attention: 64 q-rows per CTA, 128 threads, 2 CTAs/SM
    attn_mma_kernel<<<dim3(S_ / 64, B_ * H_), 128, ATTN_SMEM>>>();

    // O projection
    mma_gemm<0><<<dim3(HID_ / 128, M_ / 128), 256, GEMM_SMEM>>>(out);
}